// round 1
// baseline (speedup 1.0000x reference)
#include <cuda_runtime.h>
#include <cuda_bf16.h>
#include <cstdint>

// ---------------------------------------------------------------------------
// RouteNTMMatrix: out[b] = fc_b
//   + sum_k fc_w[k] * relu( sum_d r[d]*t[d]*w[d][k] )
//   + sum_{i,j} fc_w[100+5i+j] * sigmoid( (r@mode_a)[i]*(t@mode_b)[j] + bias[i][j] )
// r = route_table[route_idx[b]], t = time_table[time_idx[b]], D=256, K=100, C=5
// ---------------------------------------------------------------------------

#define DIM   256
#define KOUT  100
#define CDIM  5

// Scratch for precomputed projections (ra = route_table @ mode_a, tb = time_table @ mode_b)
__device__ float g_ra[100000 * CDIM];
__device__ float g_tb[2048   * CDIM];

// Packed f32x2 FMA (sm_103a FFMA2): acc = a*b + acc, elementwise on packed pairs.
#define FMA2(acc, a, b) \
    asm("fma.rn.f32x2 %0, %1, %2, %0;" : "+l"(acc) : "l"(a), "l"(b))

// ---------------------------------------------------------------------------
// Precompute kernel: one warp per table row; out[row][c] = sum_d table[row][d]*proj[d][c]
// ---------------------------------------------------------------------------
__global__ void proj_kernel(const float* __restrict__ table,
                            const float* __restrict__ proj,
                            float* __restrict__ outtab, int n)
{
    int gwarp = (blockIdx.x * blockDim.x + threadIdx.x) >> 5;
    int lane  = threadIdx.x & 31;
    if (gwarp >= n) return;

    const float* row = table + (size_t)gwarp * DIM;
    float p0 = 0.f, p1 = 0.f, p2 = 0.f, p3 = 0.f, p4 = 0.f;
#pragma unroll
    for (int it = 0; it < DIM / 32; it++) {
        int d = lane + it * 32;
        float rv = __ldg(row + d);
        const float* pr = proj + d * CDIM;
        p0 = fmaf(rv, __ldg(pr + 0), p0);
        p1 = fmaf(rv, __ldg(pr + 1), p1);
        p2 = fmaf(rv, __ldg(pr + 2), p2);
        p3 = fmaf(rv, __ldg(pr + 3), p3);
        p4 = fmaf(rv, __ldg(pr + 4), p4);
    }
#pragma unroll
    for (int off = 16; off; off >>= 1) {
        p0 += __shfl_xor_sync(0xffffffffu, p0, off);
        p1 += __shfl_xor_sync(0xffffffffu, p1, off);
        p2 += __shfl_xor_sync(0xffffffffu, p2, off);
        p3 += __shfl_xor_sync(0xffffffffu, p3, off);
        p4 += __shfl_xor_sync(0xffffffffu, p4, off);
    }
    if (lane == 0) {
        float* o = outtab + (size_t)gwarp * CDIM;
        o[0] = p0; o[1] = p1; o[2] = p2; o[3] = p3; o[4] = p4;
    }
}

// ---------------------------------------------------------------------------
// Main kernel: one element per thread; w staged in dynamic smem (100 KB),
// 50 packed-f32x2 accumulators over K=100.
// ---------------------------------------------------------------------------
__global__ __launch_bounds__(512, 1)
void main_kernel(const int*   __restrict__ route_idx,
                 const int*   __restrict__ time_idx,
                 const float* __restrict__ route_table,
                 const float* __restrict__ time_table,
                 const float* __restrict__ w,         // [256][100] row-major
                 const float* __restrict__ fc_w,      // [125]
                 const float* __restrict__ fc_b,      // [1]
                 const float* __restrict__ mode_bias, // [5][5]
                 const float* __restrict__ ra_tab,    // [n_routes][5]
                 const float* __restrict__ tb_tab,    // [n_time][5]
                 float*       __restrict__ out,
                 int batch)
{
    extern __shared__ float ws[];          // [256*100] floats = 100 KB
    __shared__ float fcs[128];             // fc_w
    __shared__ float sbias[32];            // mode_bias

    const int tid = threadIdx.x;

    // Stage w (coalesced) + small params
    for (int i = tid; i < DIM * KOUT; i += 512) ws[i] = w[i];
    if (tid < KOUT + CDIM * CDIM) fcs[tid] = fc_w[tid];
    if (tid >= 128 && tid < 128 + CDIM * CDIM) sbias[tid - 128] = mode_bias[tid - 128];
    __syncthreads();

    const int b = blockIdx.x * 512 + tid;
    if (b >= batch) return;

    const int ri = route_idx[b];
    const int ti = time_idx[b];
    const float4* r4 = reinterpret_cast<const float4*>(route_table) + (size_t)ri * (DIM / 4);
    const float4* t4 = reinterpret_cast<const float4*>(time_table)  + (size_t)ti * (DIM / 4);

    unsigned long long acc[KOUT / 2];
#pragma unroll
    for (int p = 0; p < KOUT / 2; p++) acc[p] = 0ull;

    float4 rv = __ldg(r4);
    float4 tv = __ldg(t4);

    for (int j = 0; j < DIM / 4; j++) {
        float4 rn, tn;
        if (j < DIM / 4 - 1) {            // one-step prefetch
            rn = __ldg(r4 + j + 1);
            tn = __ldg(t4 + j + 1);
        }
        float pd[4];
        pd[0] = rv.x * tv.x;
        pd[1] = rv.y * tv.y;
        pd[2] = rv.z * tv.z;
        pd[3] = rv.w * tv.w;

#pragma unroll
        for (int s = 0; s < 4; s++) {
            const int d = 4 * j + s;
            unsigned int u = __float_as_uint(pd[s]);
            unsigned long long pd2 = (unsigned long long)u | ((unsigned long long)u << 32);
            const ulonglong2* wrow = reinterpret_cast<const ulonglong2*>(ws + d * KOUT);
#pragma unroll
            for (int q = 0; q < KOUT / 4; q++) {   // 25 x LDS.128, 50 x FFMA2 per d
                ulonglong2 wv = wrow[q];
                FMA2(acc[2 * q],     pd2, wv.x);
                FMA2(acc[2 * q + 1], pd2, wv.y);
            }
        }
        rv = rn; tv = tn;
    }

    // Epilogue: relu + fc over K, then the 5x5 sigmoid interaction block.
    float sum = __ldg(fc_b);
#pragma unroll
    for (int p = 0; p < KOUT / 2; p++) {
        float lo = __uint_as_float((unsigned int)(acc[p] & 0xffffffffull));
        float hi = __uint_as_float((unsigned int)(acc[p] >> 32));
        sum = fmaf(fcs[2 * p],     fmaxf(lo, 0.f), sum);
        sum = fmaf(fcs[2 * p + 1], fmaxf(hi, 0.f), sum);
    }

    float rav[CDIM], tbv[CDIM];
    const float* rap = ra_tab + (size_t)ri * CDIM;
    const float* tbp = tb_tab + (size_t)ti * CDIM;
#pragma unroll
    for (int c = 0; c < CDIM; c++) { rav[c] = __ldg(rap + c); tbv[c] = __ldg(tbp + c); }

#pragma unroll
    for (int i = 0; i < CDIM; i++) {
#pragma unroll
        for (int jj = 0; jj < CDIM; jj++) {
            float x  = fmaf(rav[i], tbv[jj], sbias[CDIM * i + jj]);
            float sg = 1.0f / (1.0f + __expf(-x));
            sum = fmaf(fcs[KOUT + CDIM * i + jj], sg, sum);
        }
    }
    out[b] = sum;
}

// ---------------------------------------------------------------------------
extern "C" void kernel_launch(void* const* d_in, const int* in_sizes, int n_in,
                              void* d_out, int out_size)
{
    const int*   route_idx   = (const int*)  d_in[0];
    const int*   time_idx    = (const int*)  d_in[1];
    const float* route_table = (const float*)d_in[2];
    const float* time_table  = (const float*)d_in[3];
    const float* w           = (const float*)d_in[4];
    const float* mode_a      = (const float*)d_in[5];
    const float* mode_b      = (const float*)d_in[6];
    const float* mode_bias   = (const float*)d_in[7];
    const float* fc_w        = (const float*)d_in[8];
    const float* fc_b        = (const float*)d_in[9];
    float*       out         = (float*)d_out;

    const int batch    = in_sizes[0];
    const int n_routes = in_sizes[2] / DIM;
    const int n_time   = in_sizes[3] / DIM;

    float* ra_ptr = nullptr;
    float* tb_ptr = nullptr;
    cudaGetSymbolAddress((void**)&ra_ptr, g_ra);
    cudaGetSymbolAddress((void**)&tb_ptr, g_tb);

    // Precompute ra/tb tables (warp per row)
    {
        int wpb = 256 / 32;
        proj_kernel<<<(n_routes + wpb - 1) / wpb, 256>>>(route_table, mode_a, ra_ptr, n_routes);
        proj_kernel<<<(n_time   + wpb - 1) / wpb, 256>>>(time_table,  mode_b, tb_ptr, n_time);
    }

    const int smem_bytes = DIM * KOUT * (int)sizeof(float);   // 102400
    static bool attr_set = false;
    cudaFuncSetAttribute(main_kernel, cudaFuncAttributeMaxDynamicSharedMemorySize, smem_bytes);
    (void)attr_set;

    int grid = (batch + 511) / 512;
    main_kernel<<<grid, 512, smem_bytes>>>(route_idx, time_idx, route_table, time_table,
                                           w, fc_w, fc_b, mode_bias,
                                           ra_ptr, tb_ptr, out, batch);
}

// round 2
// speedup vs baseline: 1.7012x; 1.7012x over previous
#include <cuda_runtime.h>
#include <cuda_bf16.h>
#include <cstdint>

// ---------------------------------------------------------------------------
// RouteNTMMatrix: out[b] = fc_b
//   + sum_k fc_w[k] * relu( sum_d r[d]*t[d]*w[d][k] )
//   + sum_{i,j} fc_w[100+5i+j] * sigmoid( (r@mode_a)[i]*(t@mode_b)[j] + bias[i][j] )
// D=256, K=100 (padded to 104), C=5, B=262144
// ---------------------------------------------------------------------------

#define DIM    256
#define KOUT   100
#define KPAD   104
#define KHALF  52
#define NACC   26        // KHALF/2 packed-f32x2 accumulators
#define CDIM   5

// Scratch: precomputed projections
__device__ float g_ra[100000 * CDIM];
__device__ float g_tb[2048   * CDIM];

// Packed f32x2 FMA (sm_103a FFMA2)
#define FMA2(acc, a, b) \
    asm("fma.rn.f32x2 %0, %1, %2, %0;" : "+l"(acc) : "l"(a), "l"(b))

// Guaranteed shared-memory 128-bit load as two 64-bit packed values
#define LDS_V2U64(a, b, addr) \
    asm volatile("ld.shared.v2.u64 {%0, %1}, [%2];" : "=l"(a), "=l"(b) : "r"(addr))

#define PACK_DUP(out64, f) \
    asm("mov.b64 %0, {%1, %1};" : "=l"(out64) : "r"(__float_as_uint(f)))

// ---------------------------------------------------------------------------
// Fused projection kernel: warp per row over (route rows ++ time rows).
// out[row][c] = sum_d table[row][d] * proj[d][c]
// ---------------------------------------------------------------------------
__global__ __launch_bounds__(512)
void proj_fused(const float* __restrict__ route_table,
                const float* __restrict__ time_table,
                const float* __restrict__ mode_a,
                const float* __restrict__ mode_b,
                float* __restrict__ ra_tab,
                float* __restrict__ tb_tab,
                int n_routes, int n_time)
{
    __shared__ float sA[CDIM * DIM];   // transposed: sA[c*256 + d]
    __shared__ float sB[CDIM * DIM];

    const int tid = threadIdx.x;
    for (int i = tid; i < CDIM * DIM; i += 512) {
        int d = i / CDIM, c = i % CDIM;
        sA[c * DIM + d] = mode_a[i];
        sB[c * DIM + d] = mode_b[i];
    }
    __syncthreads();

    const int gwarp = (blockIdx.x * 512 + tid) >> 5;
    const int lane  = tid & 31;
    const int total = n_routes + n_time;
    if (gwarp >= total) return;

    const bool is_route = (gwarp < n_routes);
    const float4* row4 = reinterpret_cast<const float4*>(
        is_route ? (route_table + (size_t)gwarp * DIM)
                 : (time_table + (size_t)(gwarp - n_routes) * DIM));
    const float* P = is_route ? sA : sB;

    float p[CDIM];
#pragma unroll
    for (int c = 0; c < CDIM; c++) p[c] = 0.f;

#pragma unroll
    for (int it = 0; it < 2; it++) {
        const int v = lane + 32 * it;       // float4 index
        const int d0 = v * 4;
        float4 rv = __ldg(row4 + v);
#pragma unroll
        for (int c = 0; c < CDIM; c++) {
            const float* pc = P + c * DIM + d0;
            p[c] = fmaf(rv.x, pc[0], p[c]);
            p[c] = fmaf(rv.y, pc[1], p[c]);
            p[c] = fmaf(rv.z, pc[2], p[c]);
            p[c] = fmaf(rv.w, pc[3], p[c]);
        }
    }
#pragma unroll
    for (int off = 16; off; off >>= 1)
#pragma unroll
        for (int c = 0; c < CDIM; c++)
            p[c] += __shfl_xor_sync(0xffffffffu, p[c], off);

    if (lane == 0) {
        float* o = is_route ? (ra_tab + (size_t)gwarp * CDIM)
                            : (tb_tab + (size_t)(gwarp - n_routes) * CDIM);
#pragma unroll
        for (int c = 0; c < CDIM; c++) o[c] = p[c];
    }
}

// ---------------------------------------------------------------------------
// Main kernel: 2 threads per element (K split 52/52), 256 elements/block.
// w staged zero-padded to [256][104] in dynamic smem.
// ---------------------------------------------------------------------------
__global__ __launch_bounds__(512, 1)
void main_kernel(const int*   __restrict__ route_idx,
                 const int*   __restrict__ time_idx,
                 const float* __restrict__ route_table,
                 const float* __restrict__ time_table,
                 const float* __restrict__ w,         // [256][100]
                 const float* __restrict__ fc_w,      // [125]
                 const float* __restrict__ fc_b,      // [1]
                 const float* __restrict__ mode_bias, // [25]
                 const float* __restrict__ ra_tab,
                 const float* __restrict__ tb_tab,
                 float*       __restrict__ out,
                 int batch)
{
    extern __shared__ float ws[];            // [256][104] = 106496 B
    __shared__ float fcs_k[KPAD];            // fc_w[0..99], zero-padded
    __shared__ float fcs_i[CDIM * CDIM];
    __shared__ float sbias[CDIM * CDIM];

    const int tid = threadIdx.x;

    for (int i = tid; i < DIM * KPAD; i += 512) {
        int d = i / KPAD, k = i - d * KPAD;
        ws[i] = (k < KOUT) ? w[d * KOUT + k] : 0.f;
    }
    if (tid < KPAD)                      fcs_k[tid] = (tid < KOUT) ? fc_w[tid] : 0.f;
    if (tid >= 128 && tid < 128 + 25)    fcs_i[tid - 128] = fc_w[KOUT + (tid - 128)];
    if (tid >= 160 && tid < 160 + 25)    sbias[tid - 160] = mode_bias[tid - 160];
    __syncthreads();

    const int e = blockIdx.x * 256 + (tid >> 1);
    const int half = tid & 1;                 // 0: k in [0,52), 1: k in [52,104)
    const int kbase = half * KHALF;

    const int ri = route_idx[e];
    const int ti = time_idx[e];
    const float4* r4 = reinterpret_cast<const float4*>(route_table) + (size_t)ri * (DIM / 4);
    const float4* t4 = reinterpret_cast<const float4*>(time_table)  + (size_t)ti * (DIM / 4);

    // shared address of this thread's K-slice base
    uint32_t ws_addr;
    asm("{ .reg .u64 t0; cvta.to.shared.u64 t0, %1; cvt.u32.u64 %0, t0; }"
        : "=r"(ws_addr) : "l"(ws + kbase));

    unsigned long long acc[NACC];
#pragma unroll
    for (int a = 0; a < NACC; a++) acc[a] = 0ull;

    float4 rv = __ldg(r4);
    float4 tv = __ldg(t4);

    for (int j = 0; j < DIM / 4; j++) {
        float4 rn, tn;
        if (j < DIM / 4 - 1) { rn = __ldg(r4 + j + 1); tn = __ldg(t4 + j + 1); }

        float pd[4];
        pd[0] = rv.x * tv.x;  pd[1] = rv.y * tv.y;
        pd[2] = rv.z * tv.z;  pd[3] = rv.w * tv.w;

#pragma unroll
        for (int s = 0; s < 4; s++) {
            unsigned long long pd2;
            PACK_DUP(pd2, pd[s]);
            const uint32_t base = ws_addr + (4 * j + s) * (KPAD * 4);
#pragma unroll
            for (int q = 0; q < KHALF / 4; q++) {        // 13 x LDS.128
                unsigned long long w0, w1;
                LDS_V2U64(w0, w1, base + q * 16);
                FMA2(acc[2 * q],     pd2, w0);
                FMA2(acc[2 * q + 1], pd2, w1);
            }
        }
        rv = rn; tv = tn;
    }

    // Per-thread partial: sum over my 52 k's of fc_w[k] * relu(acc)
    float partial = 0.f;
#pragma unroll
    for (int a = 0; a < NACC; a++) {
        float lo = __uint_as_float((unsigned int)(acc[a] & 0xffffffffull));
        float hi = __uint_as_float((unsigned int)(acc[a] >> 32));
        partial = fmaf(fcs_k[kbase + 2 * a],     fmaxf(lo, 0.f), partial);
        partial = fmaf(fcs_k[kbase + 2 * a + 1], fmaxf(hi, 0.f), partial);
    }
    float other = __shfl_xor_sync(0xffffffffu, partial, 1);

    if (half == 0) {
        float sum = __ldg(fc_b) + partial + other;

        float rav[CDIM], tbv[CDIM];
        const float* rap = ra_tab + (size_t)ri * CDIM;
        const float* tbp = tb_tab + (size_t)ti * CDIM;
#pragma unroll
        for (int c = 0; c < CDIM; c++) { rav[c] = __ldg(rap + c); tbv[c] = __ldg(tbp + c); }

#pragma unroll
        for (int i = 0; i < CDIM; i++)
#pragma unroll
            for (int jj = 0; jj < CDIM; jj++) {
                float x  = fmaf(rav[i], tbv[jj], sbias[CDIM * i + jj]);
                float sg = 1.0f / (1.0f + __expf(-x));
                sum = fmaf(fcs_i[CDIM * i + jj], sg, sum);
            }
        out[e] = sum;
    }
}

// ---------------------------------------------------------------------------
extern "C" void kernel_launch(void* const* d_in, const int* in_sizes, int n_in,
                              void* d_out, int out_size)
{
    const int*   route_idx   = (const int*)  d_in[0];
    const int*   time_idx    = (const int*)  d_in[1];
    const float* route_table = (const float*)d_in[2];
    const float* time_table  = (const float*)d_in[3];
    const float* w           = (const float*)d_in[4];
    const float* mode_a      = (const float*)d_in[5];
    const float* mode_b      = (const float*)d_in[6];
    const float* mode_bias   = (const float*)d_in[7];
    const float* fc_w        = (const float*)d_in[8];
    const float* fc_b        = (const float*)d_in[9];
    float*       out         = (float*)d_out;

    const int batch    = in_sizes[0];
    const int n_routes = in_sizes[2] / DIM;
    const int n_time   = in_sizes[3] / DIM;

    float* ra_ptr = nullptr;
    float* tb_ptr = nullptr;
    cudaGetSymbolAddress((void**)&ra_ptr, g_ra);
    cudaGetSymbolAddress((void**)&tb_ptr, g_tb);

    // Fused projection precompute: 16 rows per block (warp per row)
    {
        int total = n_routes + n_time;
        int blocks = (total + 15) / 16;
        proj_fused<<<blocks, 512>>>(route_table, time_table, mode_a, mode_b,
                                    ra_ptr, tb_ptr, n_routes, n_time);
    }

    const int smem_bytes = DIM * KPAD * (int)sizeof(float);   // 106496
    cudaFuncSetAttribute(main_kernel, cudaFuncAttributeMaxDynamicSharedMemorySize, smem_bytes);

    int grid = (batch + 255) / 256;   // 256 elements per block
    main_kernel<<<grid, 512, smem_bytes>>>(route_idx, time_idx, route_table, time_table,
                                           w, fc_w, fc_b, mode_bias,
                                           ra_ptr, tb_ptr, out, batch);
}

// round 4
// speedup vs baseline: 2.2543x; 1.3252x over previous
#include <cuda_runtime.h>
#include <cstdint>

// ===========================================================================
// RouteNTMMatrix via mma.sync tf32 (HMMA path; valid on compute_103 PTX)
//   gcp[b,k] = relu( sum_d (r[b,d]*t[b,d]) * w[d,k] ),  D=256, K=100 (pad 128)
//   out[b] = fc_b + fc_w[0:100].gcp + sum_ij fc_w[100+5i+j]*sigmoid(ra_i*tb_j + bias_ij)
// ===========================================================================

#define DIM    256
#define KOUT   100
#define NKP    128          // padded GEMM N
#define MTILE  128
#define CDIM   5
#define WSTRIDE 260         // w row stride (words): (260 mod 32)=4 -> conflict-free B frags

// word offsets in dynamic smem
#define WS_W   0                         // w tf32 [128][260]
#define XS_W   (WS_W + NKP * WSTRIDE)    // x tf32 [128][128] swizzled (one K-half)
#define FCS_W  (XS_W + MTILE * 128)      // fc_w[0:100] padded to 128
#define FCI_W  (FCS_W + 128)             // 25 interaction weights
#define BIA_W  (FCI_W + 32)              // 25 biases
#define OAC_W  (BIA_W + 32)              // per-row partial accumulator [128]
#define RI_W   (OAC_W + 128)
#define TI_W   (RI_W + 128)
#define SM_WORDS (TI_W + 128)            // ~201 KB

// Precomputed projections
__device__ float g_ra[100000 * CDIM];
__device__ float g_tb[2048   * CDIM];

__device__ __forceinline__ uint32_t f2tf(float f) {
    uint32_t u; asm("cvt.rna.tf32.f32 %0, %1;" : "=r"(u) : "f"(f)); return u;
}
__device__ __forceinline__ void mma_tf32(float* d, const uint32_t* a, const uint32_t* b) {
    asm volatile("mma.sync.aligned.m16n8k8.row.col.f32.tf32.tf32.f32 "
                 "{%0,%1,%2,%3}, {%4,%5,%6,%7}, {%8,%9}, {%0,%1,%2,%3};"
                 : "+f"(d[0]), "+f"(d[1]), "+f"(d[2]), "+f"(d[3])
                 : "r"(a[0]), "r"(a[1]), "r"(a[2]), "r"(a[3]), "r"(b[0]), "r"(b[1]));
}

// ---------------------------------------------------------------------------
// Projection precompute: warp per row (ra = route@mode_a, tb = time@mode_b)
// ---------------------------------------------------------------------------
__global__ __launch_bounds__(256)
void proj_fused(const float* __restrict__ route_table,
                const float* __restrict__ time_table,
                const float* __restrict__ mode_a,
                const float* __restrict__ mode_b,
                float* __restrict__ ra_tab, float* __restrict__ tb_tab,
                int n_routes, int n_time)
{
    __shared__ float sA[DIM * CDIM];
    __shared__ float sB[DIM * CDIM];
    const int tid = threadIdx.x;
    for (int i = tid; i < DIM * CDIM; i += 256) { sA[i] = mode_a[i]; sB[i] = mode_b[i]; }
    __syncthreads();

    const int gwarp = (blockIdx.x * 256 + tid) >> 5;
    const int lane  = tid & 31;
    if (gwarp >= n_routes + n_time) return;

    const bool is_r = gwarp < n_routes;
    const float* row = is_r ? (route_table + (size_t)gwarp * DIM)
                            : (time_table  + (size_t)(gwarp - n_routes) * DIM);
    const float* P = is_r ? sA : sB;

    float acc[CDIM] = {0.f, 0.f, 0.f, 0.f, 0.f};
#pragma unroll
    for (int it = 0; it < DIM / 32; it++) {
        const int d = lane + 32 * it;
        const float v = __ldg(row + d);
        const float* pc = P + d * CDIM;
#pragma unroll
        for (int c = 0; c < CDIM; c++) acc[c] = fmaf(v, pc[c], acc[c]);
    }
#pragma unroll
    for (int off = 16; off; off >>= 1)
#pragma unroll
        for (int c = 0; c < CDIM; c++) acc[c] += __shfl_xor_sync(0xffffffffu, acc[c], off);

    if (lane == 0) {
        float* o = is_r ? (ra_tab + (size_t)gwarp * CDIM)
                        : (tb_tab + (size_t)(gwarp - n_routes) * CDIM);
#pragma unroll
        for (int c = 0; c < CDIM; c++) o[c] = acc[c];
    }
}

// ---------------------------------------------------------------------------
// Main persistent kernel: 256 threads (8 mma warps), tile = 128 batch rows.
// K processed in 2 halves of 128 through a single x smem buffer.
// ---------------------------------------------------------------------------
__global__ __launch_bounds__(256, 1)
void main_kernel(const int*   __restrict__ route_idx,
                 const int*   __restrict__ time_idx,
                 const float* __restrict__ route_table,
                 const float* __restrict__ time_table,
                 const float* __restrict__ w,          // [256][100]
                 const float* __restrict__ fc_w,       // [125]
                 const float* __restrict__ fc_b,       // [1]
                 const float* __restrict__ mode_bias,  // [25]
                 const float* __restrict__ ra_tab,
                 const float* __restrict__ tb_tab,
                 float*       __restrict__ out,
                 int batch, int ntiles)
{
    extern __shared__ uint32_t smu[];
    uint32_t* ws  = smu + WS_W;
    uint32_t* xs  = smu + XS_W;
    float*    fcs = reinterpret_cast<float*>(smu + FCS_W);
    float*    fci = reinterpret_cast<float*>(smu + FCI_W);
    float*    bia = reinterpret_cast<float*>(smu + BIA_W);
    float*    oac = reinterpret_cast<float*>(smu + OAC_W);
    int*      ris = reinterpret_cast<int*>(smu + RI_W);
    int*      tis = reinterpret_cast<int*>(smu + TI_W);

    const int tid  = threadIdx.x;
    const int wid  = tid >> 5;
    const int lane = tid & 31;

    // ---- stage w as tf32, layout [n][k] stride 260, zero-padded n>=100 ----
    for (int i = tid; i < DIM * NKP; i += 256) {
        const int k = i >> 7, n = i & 127;
        const float v = (n < KOUT) ? __ldg(w + k * KOUT + n) : 0.f;
        ws[n * WSTRIDE + k] = f2tf(v);
    }
    if (tid < 128) fcs[tid] = (tid < KOUT) ? __ldg(fc_w + tid) : 0.f;
    if (tid >= 128 && tid < 153) fci[tid - 128] = __ldg(fc_w + KOUT + tid - 128);
    if (tid >= 160 && tid < 185) bia[tid - 160] = __ldg(mode_bias + tid - 160);
    __syncthreads();

    const float fcb = __ldg(fc_b);

    // mma warp mapping: mh = rows half (64), nq = col quarter (32)
    const int mh = wid >> 2;
    const int nq = wid & 3;
    const int r  = lane >> 2;      // fragment row-in-8
    const int c  = lane & 3;       // fragment col-in-4
    // gather mapping
    const int gm = tid >> 1;       // row within tile
    const int gh = tid & 1;        // 64-col half of a K-half

    for (int tile = blockIdx.x; tile < ntiles; tile += gridDim.x) {
        const int e = tile * MTILE + gm;
        const bool gvalid = (e < batch);
        const int ri = gvalid ? __ldg(route_idx + e) : 0;
        const int ti = gvalid ? __ldg(time_idx  + e) : 0;
        const float4* r4 = reinterpret_cast<const float4*>(route_table) + (size_t)ri * (DIM / 4);
        const float4* t4 = reinterpret_cast<const float4*>(time_table)  + (size_t)ti * (DIM / 4);
        if (gh == 0) { ris[gm] = ri; tis[gm] = ti; }
        if (tid < MTILE) oac[tid] = 0.f;

        float acc[4][4][4];
#pragma unroll
        for (int m = 0; m < 4; m++)
#pragma unroll
            for (int n = 0; n < 4; n++)
#pragma unroll
                for (int q = 0; q < 4; q++) acc[m][n][q] = 0.f;

#pragma unroll
        for (int half = 0; half < 2; half++) {
            // ---- gather: x[gm][gh*64 .. +63] = tf32(r*t), swizzled ----
            {
                const int sw = (gm & 7) << 2;
                const int f0 = half * 32 + gh * 16;
#pragma unroll
                for (int j = 0; j < 16; j++) {
                    const float4 rv = __ldg(r4 + f0 + j);
                    const float4 tv = __ldg(t4 + f0 + j);
                    uint4 xv;
                    xv.x = f2tf(rv.x * tv.x);
                    xv.y = f2tf(rv.y * tv.y);
                    xv.z = f2tf(rv.z * tv.z);
                    xv.w = f2tf(rv.w * tv.w);
                    const int kl = gh * 64 + j * 4;
                    *reinterpret_cast<uint4*>(xs + gm * 128 + (kl ^ sw)) = xv;
                }
            }
            __syncthreads();

            // ---- mma over this K-half: 16 chunks of k8 ----
#pragma unroll 4
            for (int kc = 0; kc < 16; kc++) {
                const int kg = half * 128 + kc * 8;
                uint32_t b[4][2];
#pragma unroll
                for (int n = 0; n < 4; n++) {
                    const int nn = nq * 32 + n * 8 + r;
                    b[n][0] = ws[nn * WSTRIDE + kg + c];
                    b[n][1] = ws[nn * WSTRIDE + kg + 4 + c];
                }
#pragma unroll
                for (int m = 0; m < 4; m++) {
                    const int rowa = mh * 64 + m * 16 + r;
                    const int sw   = r << 2;             // (rowa&7)<<2 == (rowa+8&7)<<2
                    const int kl   = kc * 8;
                    uint32_t a[4];
                    a[0] = xs[rowa * 128 + ((kl + c) ^ sw)];
                    a[1] = xs[(rowa + 8) * 128 + ((kl + c) ^ sw)];
                    a[2] = xs[rowa * 128 + ((kl + c + 4) ^ sw)];
                    a[3] = xs[(rowa + 8) * 128 + ((kl + c + 4) ^ sw)];
#pragma unroll
                    for (int n = 0; n < 4; n++) mma_tf32(acc[m][n], a, b[n]);
                }
            }
            __syncthreads();   // x buffer reuse / epilogue ordering
        }

        // ---- epilogue: fold relu * fc_w, reduce to per-row partials ----
#pragma unroll
        for (int m = 0; m < 4; m++) {
            float p0 = 0.f, p1 = 0.f;
#pragma unroll
            for (int n = 0; n < 4; n++) {
                const int col = nq * 32 + n * 8 + 2 * c;
                const float f0 = fcs[col], f1 = fcs[col + 1];
                p0 = fmaf(f0, fmaxf(acc[m][n][0], 0.f), p0);
                p0 = fmaf(f1, fmaxf(acc[m][n][1], 0.f), p0);
                p1 = fmaf(f0, fmaxf(acc[m][n][2], 0.f), p1);
                p1 = fmaf(f1, fmaxf(acc[m][n][3], 0.f), p1);
            }
            p0 += __shfl_xor_sync(0xffffffffu, p0, 1);
            p0 += __shfl_xor_sync(0xffffffffu, p0, 2);
            p1 += __shfl_xor_sync(0xffffffffu, p1, 1);
            p1 += __shfl_xor_sync(0xffffffffu, p1, 2);
            if (c == 0) {
                const int row = mh * 64 + m * 16 + r;
                atomicAdd(oac + row, p0);
                atomicAdd(oac + row + 8, p1);
            }
        }
        __syncthreads();

        // ---- finalize rows: add interaction block + store ----
        if (tid < MTILE) {
            const int row = tid;
            const int eo  = tile * MTILE + row;
            if (eo < batch) {
                float sum = fcb + oac[row];
                const float* rap = ra_tab + (size_t)ris[row] * CDIM;
                const float* tbp = tb_tab + (size_t)tis[row] * CDIM;
                float rav[CDIM], tbv[CDIM];
#pragma unroll
                for (int q = 0; q < CDIM; q++) { rav[q] = __ldg(rap + q); tbv[q] = __ldg(tbp + q); }
#pragma unroll
                for (int i = 0; i < CDIM; i++)
#pragma unroll
                    for (int j = 0; j < CDIM; j++) {
                        const float x  = fmaf(rav[i], tbv[j], bia[CDIM * i + j]);
                        const float sg = 1.0f / (1.0f + __expf(-x));
                        sum = fmaf(fci[CDIM * i + j], sg, sum);
                    }
                out[eo] = sum;
            }
        }
        __syncthreads();   // protect oac/ris/xs before next tile
    }
}

// ---------------------------------------------------------------------------
extern "C" void kernel_launch(void* const* d_in, const int* in_sizes, int n_in,
                              void* d_out, int out_size)
{
    const int*   route_idx   = (const int*)  d_in[0];
    const int*   time_idx    = (const int*)  d_in[1];
    const float* route_table = (const float*)d_in[2];
    const float* time_table  = (const float*)d_in[3];
    const float* w           = (const float*)d_in[4];
    const float* mode_a      = (const float*)d_in[5];
    const float* mode_b      = (const float*)d_in[6];
    const float* mode_bias   = (const float*)d_in[7];
    const float* fc_w        = (const float*)d_in[8];
    const float* fc_b        = (const float*)d_in[9];
    float*       out         = (float*)d_out;

    const int batch    = in_sizes[0];
    const int n_routes = in_sizes[2] / DIM;
    const int n_time   = in_sizes[3] / DIM;

    float *ra_ptr = nullptr, *tb_ptr = nullptr;
    cudaGetSymbolAddress((void**)&ra_ptr, g_ra);
    cudaGetSymbolAddress((void**)&tb_ptr, g_tb);

    {
        const int total = n_routes + n_time;
        proj_fused<<<(total + 7) / 8, 256>>>(route_table, time_table, mode_a, mode_b,
                                             ra_ptr, tb_ptr, n_routes, n_time);
    }

    const int ntiles = (batch + MTILE - 1) / MTILE;
    const int smem_bytes = SM_WORDS * 4;
    cudaFuncSetAttribute(main_kernel, cudaFuncAttributeMaxDynamicSharedMemorySize, smem_bytes);

    int grid = 148;
    if (grid > ntiles) grid = ntiles;
    main_kernel<<<grid, 256, smem_bytes>>>(route_idx, time_idx, route_table, time_table,
                                           w, fc_w, fc_b, mode_bias,
                                           ra_ptr, tb_ptr, out, batch, ntiles);
}

// round 5
// speedup vs baseline: 2.6339x; 1.1684x over previous
#include <cuda_runtime.h>
#include <cstdint>

// ===========================================================================
// RouteNTMMatrix via bf16 mma.sync.m16n8k16 (plain PTX, compute_103-safe)
//   gcp[b,k] = relu( sum_d (r[b,d]*t[b,d]) * w[d,k] ),  D=256, K=100 (pad 128)
//   out[b] = fc_b + fc_w[0:100].gcp + sum_ij fc_w[100+5i+j]*sigmoid(ra_i*tb_j+bias_ij)
// Persistent, double-buffered x tile, 512 threads.
// ===========================================================================

#define DIM    256
#define KOUT   100
#define MTILE  128
#define CDIM   5
#define XSTR   132            // row stride in words (uint32 bf16-pairs); 132%32=4 -> conflict-free

// word offsets in dynamic smem
#define WP_W   0                          // w bf16-pairs [128n][132]
#define XB_W   (WP_W + 128 * XSTR)        // x bf16-pairs, 2 buffers [128][132]
#define FCS_W  (XB_W + 2 * 128 * XSTR)    // fc_w[0:100] padded 128
#define FCI_W  (FCS_W + 128)              // 25 interaction weights
#define BIA_W  (FCI_W + 32)               // 25 biases
#define OAC_W  (BIA_W + 32)               // per-row partials [128]
#define RIS_W  (OAC_W + 128)              // route idx, 2 buffers [128]
#define TIS_W  (RIS_W + 256)              // time idx, 2 buffers [128]
#define SM_WORDS (TIS_W + 256)            // ~206 KB

__device__ float g_ra[100000 * CDIM];
__device__ float g_tb[2048   * CDIM];

__device__ __forceinline__ uint32_t pack_bf16(float lo, float hi) {
    uint32_t u;
    asm("cvt.rn.bf16x2.f32 %0, %1, %2;" : "=r"(u) : "f"(hi), "f"(lo));
    return u;
}
__device__ __forceinline__ void mma_bf16(float* d, const uint32_t* a, const uint32_t* b) {
    asm volatile("mma.sync.aligned.m16n8k16.row.col.f32.bf16.bf16.f32 "
                 "{%0,%1,%2,%3}, {%4,%5,%6,%7}, {%8,%9}, {%0,%1,%2,%3};"
                 : "+f"(d[0]), "+f"(d[1]), "+f"(d[2]), "+f"(d[3])
                 : "r"(a[0]), "r"(a[1]), "r"(a[2]), "r"(a[3]), "r"(b[0]), "r"(b[1]));
}

// Gather + multiply + pack one (row, 64-col quarter): 16 LDG.128 pairs -> 32 bf16x2
__device__ __forceinline__ void gather_pack(const float4* r4, const float4* t4,
                                            int gq, uint32_t* P) {
#pragma unroll
    for (int h = 0; h < 2; h++) {
        float4 rv[8], tv[8];
#pragma unroll
        for (int j = 0; j < 8; j++) {
            rv[j] = __ldg(r4 + gq * 16 + h * 8 + j);
            tv[j] = __ldg(t4 + gq * 16 + h * 8 + j);
        }
#pragma unroll
        for (int j = 0; j < 8; j++) {
            P[h * 16 + j * 2]     = pack_bf16(rv[j].x * tv[j].x, rv[j].y * tv[j].y);
            P[h * 16 + j * 2 + 1] = pack_bf16(rv[j].z * tv[j].z, rv[j].w * tv[j].w);
        }
    }
}

// ---------------------------------------------------------------------------
// Projection precompute: warp per row (ra = route@mode_a, tb = time@mode_b)
// ---------------------------------------------------------------------------
__global__ __launch_bounds__(256)
void proj_fused(const float* __restrict__ route_table,
                const float* __restrict__ time_table,
                const float* __restrict__ mode_a,
                const float* __restrict__ mode_b,
                float* __restrict__ ra_tab, float* __restrict__ tb_tab,
                int n_routes, int n_time)
{
    __shared__ float sA[DIM * CDIM];
    __shared__ float sB[DIM * CDIM];
    const int tid = threadIdx.x;
    for (int i = tid; i < DIM * CDIM; i += 256) { sA[i] = mode_a[i]; sB[i] = mode_b[i]; }
    __syncthreads();

    const int gwarp = (blockIdx.x * 256 + tid) >> 5;
    const int lane  = tid & 31;
    if (gwarp >= n_routes + n_time) return;

    const bool is_r = gwarp < n_routes;
    const float* row = is_r ? (route_table + (size_t)gwarp * DIM)
                            : (time_table  + (size_t)(gwarp - n_routes) * DIM);
    const float* P = is_r ? sA : sB;

    float acc[CDIM] = {0.f, 0.f, 0.f, 0.f, 0.f};
#pragma unroll
    for (int it = 0; it < DIM / 32; it++) {
        const int d = lane + 32 * it;
        const float v = __ldg(row + d);
        const float* pc = P + d * CDIM;
#pragma unroll
        for (int c = 0; c < CDIM; c++) acc[c] = fmaf(v, pc[c], acc[c]);
    }
#pragma unroll
    for (int off = 16; off; off >>= 1)
#pragma unroll
        for (int c = 0; c < CDIM; c++) acc[c] += __shfl_xor_sync(0xffffffffu, acc[c], off);

    if (lane == 0) {
        float* o = is_r ? (ra_tab + (size_t)gwarp * CDIM)
                        : (tb_tab + (size_t)(gwarp - n_routes) * CDIM);
#pragma unroll
        for (int c = 0; c < CDIM; c++) o[c] = acc[c];
    }
}

// ---------------------------------------------------------------------------
// Main persistent kernel: 512 threads, 16 mma warps, tile = 128 rows,
// software-pipelined gather(j+1) || mma(j) with double-buffered x.
// ---------------------------------------------------------------------------
__global__ __launch_bounds__(512, 1)
void main_kernel(const int*   __restrict__ route_idx,
                 const int*   __restrict__ time_idx,
                 const float* __restrict__ route_table,
                 const float* __restrict__ time_table,
                 const float* __restrict__ w,          // [256][100]
                 const float* __restrict__ fc_w,       // [125]
                 const float* __restrict__ fc_b,       // [1]
                 const float* __restrict__ mode_bias,  // [25]
                 const float* __restrict__ ra_tab,
                 const float* __restrict__ tb_tab,
                 float*       __restrict__ out,
                 int batch, int ntiles)
{
    extern __shared__ uint32_t smu[];
    uint32_t* wp  = smu + WP_W;
    float*    fcs = reinterpret_cast<float*>(smu + FCS_W);
    float*    fci = reinterpret_cast<float*>(smu + FCI_W);
    float*    bia = reinterpret_cast<float*>(smu + BIA_W);
    float*    oac = reinterpret_cast<float*>(smu + OAC_W);
    int*      ris = reinterpret_cast<int*>(smu + RIS_W);
    int*      tis = reinterpret_cast<int*>(smu + TIS_W);

    const int tid  = threadIdx.x;
    const int wid  = tid >> 5;
    const int lane = tid & 31;

    // ---- stage w as bf16 pairs: wp[n*132 + kp] = {bf16(w[2kp][n]), bf16(w[2kp+1][n])} ----
    for (int i = tid; i < 128 * 128; i += 512) {
        const int n = i & 127, kp = i >> 7;
        const float f0 = (n < KOUT) ? __ldg(w + (2 * kp)     * KOUT + n) : 0.f;
        const float f1 = (n < KOUT) ? __ldg(w + (2 * kp + 1) * KOUT + n) : 0.f;
        wp[n * XSTR + kp] = pack_bf16(f0, f1);
    }
    if (tid < 128)                 fcs[tid] = (tid < KOUT) ? __ldg(fc_w + tid) : 0.f;
    if (tid >= 128 && tid < 153)   fci[tid - 128] = __ldg(fc_w + KOUT + tid - 128);
    if (tid >= 160 && tid < 185)   bia[tid - 160] = __ldg(mode_bias + tid - 160);
    if (tid < 128)                 oac[tid] = 0.f;
    __syncthreads();

    const float fcb = __ldg(fc_b);

    // mma mapping: warp = (mq, nq); fragment lane = (g, t)
    const int mq = wid >> 2, nq = wid & 3;
    const int g  = lane >> 2, t = lane & 3;
    // gather mapping: 4 threads per row
    const int gm = tid >> 2;        // row 0..127
    const int gq = tid & 3;         // 64-col quarter

    const int grid = gridDim.x;
    uint32_t P[32];
    int ri = 0, ti = 0;

    // prologue: pack first tile
    {
        const int tile0 = blockIdx.x;
        if (tile0 < ntiles) {
            const int e = tile0 * MTILE + gm;
            const bool v = (e < batch);
            ri = v ? __ldg(route_idx + e) : 0;
            ti = v ? __ldg(time_idx  + e) : 0;
            const float4* r4 = reinterpret_cast<const float4*>(route_table) + (size_t)ri * (DIM / 4);
            const float4* t4 = reinterpret_cast<const float4*>(time_table)  + (size_t)ti * (DIM / 4);
            gather_pack(r4, t4, gq, P);
        }
    }

    int it = 0;
    for (int tile = blockIdx.x; tile < ntiles; tile += grid, it++) {
        const int cur = it & 1;
        uint32_t* xb = smu + XB_W + cur * (128 * XSTR);

        // ---- (a) STS packed tile j; record indices ----
        {
            uint32_t* dst = xb + gm * XSTR + gq * 32;
#pragma unroll
            for (int jj = 0; jj < 8; jj++) {
                uint4 v4 = make_uint4(P[4 * jj], P[4 * jj + 1], P[4 * jj + 2], P[4 * jj + 3]);
                *reinterpret_cast<uint4*>(dst + 4 * jj) = v4;
            }
            if (gq == 0) { ris[cur * 128 + gm] = ri; tis[cur * 128 + gm] = ti; }
        }

        // ---- (b) gather + pack tile j+1 (LDG latency overlaps other warps' mma) ----
        {
            const int nt2 = tile + grid;
            if (nt2 < ntiles) {
                const int e = nt2 * MTILE + gm;
                const bool v = (e < batch);
                ri = v ? __ldg(route_idx + e) : 0;
                ti = v ? __ldg(time_idx  + e) : 0;
                const float4* r4 = reinterpret_cast<const float4*>(route_table) + (size_t)ri * (DIM / 4);
                const float4* t4 = reinterpret_cast<const float4*>(time_table)  + (size_t)ti * (DIM / 4);
                gather_pack(r4, t4, gq, P);
            }
        }

        __syncthreads();   // STS(j) visible to all before mma(j)

        // ---- (c) mma over K: 16 chunks of k16 ----
        float acc[2][4][4];
#pragma unroll
        for (int m = 0; m < 2; m++)
#pragma unroll
            for (int n = 0; n < 4; n++)
#pragma unroll
                for (int q = 0; q < 4; q++) acc[m][n][q] = 0.f;

        const uint32_t* xrow0 = xb + (mq * 32 + g) * XSTR + t;       // rows mq*32+g (+16 for mt1)
        const uint32_t* wrow0 = wp + (nq * 32 + g) * XSTR + t;       // cols nq*32+g (+8 per nt)

#pragma unroll 2
        for (int kc = 0; kc < 16; kc++) {
            const int ko = kc * 8;
            uint32_t b[4][2];
#pragma unroll
            for (int n = 0; n < 4; n++) {
                b[n][0] = wrow0[n * (8 * XSTR) + ko];
                b[n][1] = wrow0[n * (8 * XSTR) + ko + 4];
            }
#pragma unroll
            for (int m = 0; m < 2; m++) {
                uint32_t a[4];
                const uint32_t* xr = xrow0 + m * (16 * XSTR);
                a[0] = xr[ko];
                a[1] = xr[8 * XSTR + ko];
                a[2] = xr[ko + 4];
                a[3] = xr[8 * XSTR + ko + 4];
#pragma unroll
                for (int n = 0; n < 4; n++) mma_bf16(acc[m][n], a, b[n]);
            }
        }

        // ---- (d) fold relu * fc_w -> per-row partials ----
#pragma unroll
        for (int m = 0; m < 2; m++) {
            float p0 = 0.f, p1 = 0.f;
#pragma unroll
            for (int n = 0; n < 4; n++) {
                const int col = nq * 32 + n * 8 + 2 * t;
                const float f0 = fcs[col], f1 = fcs[col + 1];
                p0 = fmaf(f0, fmaxf(acc[m][n][0], 0.f), p0);
                p0 = fmaf(f1, fmaxf(acc[m][n][1], 0.f), p0);
                p1 = fmaf(f0, fmaxf(acc[m][n][2], 0.f), p1);
                p1 = fmaf(f1, fmaxf(acc[m][n][3], 0.f), p1);
            }
            p0 += __shfl_xor_sync(0xffffffffu, p0, 1);
            p0 += __shfl_xor_sync(0xffffffffu, p0, 2);
            p1 += __shfl_xor_sync(0xffffffffu, p1, 1);
            p1 += __shfl_xor_sync(0xffffffffu, p1, 2);
            if (t == 0) {
                const int row = mq * 32 + m * 16 + g;
                atomicAdd(oac + row, p0);
                atomicAdd(oac + row + 8, p1);
            }
        }
        __syncthreads();   // partials complete

        // ---- (e) finalize 128 rows ----
        if (tid < MTILE) {
            const int eo = tile * MTILE + tid;
            if (eo < batch) {
                float sum = fcb + oac[tid];
                const float* rap = ra_tab + (size_t)ris[cur * 128 + tid] * CDIM;
                const float* tbp = tb_tab + (size_t)tis[cur * 128 + tid] * CDIM;
                float rav[CDIM], tbv[CDIM];
#pragma unroll
                for (int q = 0; q < CDIM; q++) { rav[q] = __ldg(rap + q); tbv[q] = __ldg(tbp + q); }
#pragma unroll
                for (int i = 0; i < CDIM; i++)
#pragma unroll
                    for (int j = 0; j < CDIM; j++) {
                        const float x  = fmaf(rav[i], tbv[j], bia[CDIM * i + j]);
                        const float sg = 1.0f / (1.0f + __expf(-x));
                        sum = fmaf(fci[CDIM * i + j], sg, sum);
                    }
                out[eo] = sum;
            }
            oac[tid] = 0.f;   // reset for next tile (next atomics are 2 syncs away)
        }
    }
}

// ---------------------------------------------------------------------------
extern "C" void kernel_launch(void* const* d_in, const int* in_sizes, int n_in,
                              void* d_out, int out_size)
{
    const int*   route_idx   = (const int*)  d_in[0];
    const int*   time_idx    = (const int*)  d_in[1];
    const float* route_table = (const float*)d_in[2];
    const float* time_table  = (const float*)d_in[3];
    const float* w           = (const float*)d_in[4];
    const float* mode_a      = (const float*)d_in[5];
    const float* mode_b      = (const float*)d_in[6];
    const float* mode_bias   = (const float*)d_in[7];
    const float* fc_w        = (const float*)d_in[8];
    const float* fc_b        = (const float*)d_in[9];
    float*       out         = (float*)d_out;

    const int batch    = in_sizes[0];
    const int n_routes = in_sizes[2] / DIM;
    const int n_time   = in_sizes[3] / DIM;

    float *ra_ptr = nullptr, *tb_ptr = nullptr;
    cudaGetSymbolAddress((void**)&ra_ptr, g_ra);
    cudaGetSymbolAddress((void**)&tb_ptr, g_tb);

    {
        const int total = n_routes + n_time;
        proj_fused<<<(total + 7) / 8, 256>>>(route_table, time_table, mode_a, mode_b,
                                             ra_ptr, tb_ptr, n_routes, n_time);
    }

    const int ntiles = (batch + MTILE - 1) / MTILE;
    const int smem_bytes = SM_WORDS * 4;   // ~206 KB
    cudaFuncSetAttribute(main_kernel, cudaFuncAttributeMaxDynamicSharedMemorySize, smem_bytes);

    int grid = 148;
    if (grid > ntiles) grid = ntiles;
    main_kernel<<<grid, 512, smem_bytes>>>(route_idx, time_idx, route_table, time_table,
                                           w, fc_w, fc_b, mode_bias,
                                           ra_ptr, tb_ptr, out, batch, ntiles);
}

// round 6
// speedup vs baseline: 5.3671x; 2.0377x over previous
#include <cuda_runtime.h>
#include <cstdint>

// ===========================================================================
// RouteNTMMatrix via bf16 mma.sync.m16n8k16, coalesced warp-per-row gather.
//   gcp[b,k] = relu( sum_d (r[b,d]*t[b,d]) * w[d,k] ),  D=256, K=100 (pad 128)
//   out[b] = fc_b + fc_w[0:100].gcp + sum_ij fc_w[100+5i+j]*sigmoid(ra_i*tb_j+bias_ij)
// ===========================================================================

#define DIM    256
#define KOUT   100
#define MTILE  128
#define CDIM   5
#define XSTR   132            // row stride in uint32 (bf16x2) words; 132%32=4 -> conflict-free frags

// word offsets in dynamic smem
#define WP_W   0                          // w bf16-pairs [128n][132]
#define XB_W   (WP_W + 128 * XSTR)        // x bf16-pairs, 2 buffers [128][132]
#define FCS_W  (XB_W + 2 * 128 * XSTR)    // fc_w[0:100] padded 128
#define FCI_W  (FCS_W + 128)              // 25 interaction weights
#define BIA_W  (FCI_W + 32)               // 25 biases
#define OAC_W  (BIA_W + 32)               // per-row partials [128]
#define RIS_W  (OAC_W + 128)              // route idx, 2 slots [128]
#define TIS_W  (RIS_W + 256)              // time idx, 2 slots [128]
#define SM_WORDS (TIS_W + 256)            // ~206 KB

__device__ float g_ra[100000 * CDIM];
__device__ float g_tb[2048   * CDIM];

__device__ __forceinline__ uint32_t pack_bf16(float lo, float hi) {
    uint32_t u;
    asm("cvt.rn.bf16x2.f32 %0, %1, %2;" : "=r"(u) : "f"(hi), "f"(lo));
    return u;
}
__device__ __forceinline__ void mma_bf16(float* d, const uint32_t* a, const uint32_t* b) {
    asm volatile("mma.sync.aligned.m16n8k16.row.col.f32.bf16.bf16.f32 "
                 "{%0,%1,%2,%3}, {%4,%5,%6,%7}, {%8,%9}, {%0,%1,%2,%3};"
                 : "+f"(d[0]), "+f"(d[1]), "+f"(d[2]), "+f"(d[3])
                 : "r"(a[0]), "r"(a[1]), "r"(a[2]), "r"(a[3]), "r"(b[0]), "r"(b[1]));
}
__device__ __forceinline__ uint2 pack4(float4 a, float4 b) {
    uint2 u;
    u.x = pack_bf16(a.x * b.x, a.y * b.y);
    u.y = pack_bf16(a.z * b.z, a.w * b.w);
    return u;
}

// ---------------------------------------------------------------------------
// Projection precompute: warp per row (ra = route@mode_a, tb = time@mode_b)
// ---------------------------------------------------------------------------
__global__ __launch_bounds__(256)
void proj_fused(const float* __restrict__ route_table,
                const float* __restrict__ time_table,
                const float* __restrict__ mode_a,
                const float* __restrict__ mode_b,
                float* __restrict__ ra_tab, float* __restrict__ tb_tab,
                int n_routes, int n_time)
{
    __shared__ float sA[DIM * CDIM];
    __shared__ float sB[DIM * CDIM];
    const int tid = threadIdx.x;
    for (int i = tid; i < DIM * CDIM; i += 256) { sA[i] = mode_a[i]; sB[i] = mode_b[i]; }
    __syncthreads();

    const int gwarp = (blockIdx.x * 256 + tid) >> 5;
    const int lane  = tid & 31;
    if (gwarp >= n_routes + n_time) return;

    const bool is_r = gwarp < n_routes;
    const float* row = is_r ? (route_table + (size_t)gwarp * DIM)
                            : (time_table  + (size_t)(gwarp - n_routes) * DIM);
    const float* P = is_r ? sA : sB;

    // prefetch all 8 values up front for MLP
    float v[DIM / 32];
#pragma unroll
    for (int it = 0; it < DIM / 32; it++) v[it] = __ldg(row + lane + 32 * it);

    float acc[CDIM] = {0.f, 0.f, 0.f, 0.f, 0.f};
#pragma unroll
    for (int it = 0; it < DIM / 32; it++) {
        const float* pc = P + (lane + 32 * it) * CDIM;   // stride-5: conflict-free
#pragma unroll
        for (int c = 0; c < CDIM; c++) acc[c] = fmaf(v[it], pc[c], acc[c]);
    }
#pragma unroll
    for (int off = 16; off; off >>= 1)
#pragma unroll
        for (int c = 0; c < CDIM; c++) acc[c] += __shfl_xor_sync(0xffffffffu, acc[c], off);

    if (lane == 0) {
        float* o = is_r ? (ra_tab + (size_t)gwarp * CDIM)
                        : (tb_tab + (size_t)(gwarp - n_routes) * CDIM);
#pragma unroll
        for (int c = 0; c < CDIM; c++) o[c] = acc[c];
    }
}

// ---------------------------------------------------------------------------
// Coalesced gather of one tile into x buffer `slot`.
// Warp `wid` owns rows wid*8 .. wid*8+7; 32 lanes sweep each row.
// ---------------------------------------------------------------------------
__device__ __forceinline__ void gather_tile(
    uint32_t* smu, int slot, int tile,
    const int* __restrict__ route_idx, const int* __restrict__ time_idx,
    const float4* __restrict__ RT4, const float4* __restrict__ TT4,
    int batch, int wid, int lane)
{
    uint32_t* xb  = smu + XB_W + slot * (128 * XSTR);
    int*      ris = reinterpret_cast<int*>(smu + RIS_W) + slot * 128;
    int*      tis = reinterpret_cast<int*>(smu + TIS_W) + slot * 128;

    const int rbase = tile * MTILE + wid * 8;
    const int li = lane & 7;
    const int ei = min(rbase + li, batch - 1);
    const int ridx = __ldg(route_idx + ei);
    const int tidx = __ldg(time_idx  + ei);
    if (lane < 8) { ris[wid * 8 + li] = ridx; tis[wid * 8 + li] = tidx; }

#pragma unroll
    for (int i = 0; i < 8; i += 2) {
        const int r0 = __shfl_sync(0xffffffffu, ridx, i);
        const int t0 = __shfl_sync(0xffffffffu, tidx, i);
        const int r1 = __shfl_sync(0xffffffffu, ridx, i + 1);
        const int t1 = __shfl_sync(0xffffffffu, tidx, i + 1);
        const float4* ra = RT4 + (size_t)r0 * 64;
        const float4* ta = TT4 + (size_t)t0 * 64;
        const float4* rb = RT4 + (size_t)r1 * 64;
        const float4* tb = TT4 + (size_t)t1 * 64;
        // 8 independent coalesced LDG.128 in flight
        const float4 va0 = __ldg(ra + lane),      wa0 = __ldg(ta + lane);
        const float4 va1 = __ldg(ra + 32 + lane), wa1 = __ldg(ta + 32 + lane);
        const float4 vb0 = __ldg(rb + lane),      wb0 = __ldg(tb + lane);
        const float4 vb1 = __ldg(rb + 32 + lane), wb1 = __ldg(tb + 32 + lane);

        uint32_t* d0 = xb + (wid * 8 + i) * XSTR;
        uint32_t* d1 = xb + (wid * 8 + i + 1) * XSTR;
        *reinterpret_cast<uint2*>(d0 + 2 * lane)      = pack4(va0, wa0);
        *reinterpret_cast<uint2*>(d0 + 64 + 2 * lane) = pack4(va1, wa1);
        *reinterpret_cast<uint2*>(d1 + 2 * lane)      = pack4(vb0, wb0);
        *reinterpret_cast<uint2*>(d1 + 64 + 2 * lane) = pack4(vb1, wb1);
    }
}

// ---------------------------------------------------------------------------
// Main persistent kernel: 512 threads (16 warps), tile = 128 rows,
// double-buffered x; gather(j+1) overlaps mma(j) across warps.
// ---------------------------------------------------------------------------
__global__ __launch_bounds__(512, 1)
void main_kernel(const int*   __restrict__ route_idx,
                 const int*   __restrict__ time_idx,
                 const float* __restrict__ route_table,
                 const float* __restrict__ time_table,
                 const float* __restrict__ w,          // [256][100]
                 const float* __restrict__ fc_w,       // [125]
                 const float* __restrict__ fc_b,       // [1]
                 const float* __restrict__ mode_bias,  // [25]
                 const float* __restrict__ ra_tab,
                 const float* __restrict__ tb_tab,
                 float*       __restrict__ out,
                 int batch, int ntiles)
{
    extern __shared__ uint32_t smu[];
    uint32_t* wp  = smu + WP_W;
    float*    fcs = reinterpret_cast<float*>(smu + FCS_W);
    float*    fci = reinterpret_cast<float*>(smu + FCI_W);
    float*    bia = reinterpret_cast<float*>(smu + BIA_W);
    float*    oac = reinterpret_cast<float*>(smu + OAC_W);

    const int tid  = threadIdx.x;
    const int wid  = tid >> 5;
    const int lane = tid & 31;

    const float4* RT4 = reinterpret_cast<const float4*>(route_table);
    const float4* TT4 = reinterpret_cast<const float4*>(time_table);

    // ---- stage w as bf16 pairs: wp[n*132 + kp] = {bf16(w[2kp][n]), bf16(w[2kp+1][n])} ----
    for (int i = tid; i < 128 * 128; i += 512) {
        const int n = i & 127, kp = i >> 7;
        const float f0 = (n < KOUT) ? __ldg(w + (2 * kp)     * KOUT + n) : 0.f;
        const float f1 = (n < KOUT) ? __ldg(w + (2 * kp + 1) * KOUT + n) : 0.f;
        wp[n * XSTR + kp] = pack_bf16(f0, f1);
    }
    if (tid < 128)                 fcs[tid] = (tid < KOUT) ? __ldg(fc_w + tid) : 0.f;
    if (tid >= 128 && tid < 153)   fci[tid - 128] = __ldg(fc_w + KOUT + tid - 128);
    if (tid >= 160 && tid < 185)   bia[tid - 160] = __ldg(mode_bias + tid - 160);
    if (tid < 128)                 oac[tid] = 0.f;

    const float fcb = __ldg(fc_b);

    // mma mapping: warp = (mq, nq); fragment lane = (g, t)
    const int mq = wid >> 2, nq = wid & 3;
    const int g  = lane >> 2, t = lane & 3;

    const int grid = gridDim.x;

    // prologue: gather first tile into slot 0 (also covers w-staging barrier)
    gather_tile(smu, 0, blockIdx.x, route_idx, time_idx, RT4, TT4, batch, wid, lane);
    __syncthreads();

    int it = 0;
    for (int tile = blockIdx.x; tile < ntiles; tile += grid, it++) {
        const int cur = it & 1;
        uint32_t* xb = smu + XB_W + cur * (128 * XSTR);

        // ---- (a) gather next tile into other slot (overlaps mma below across warps) ----
        if (tile + grid < ntiles)
            gather_tile(smu, cur ^ 1, tile + grid, route_idx, time_idx, RT4, TT4, batch, wid, lane);

        // ---- (b) mma over K: 16 chunks of k16 ----
        float acc[2][4][4];
#pragma unroll
        for (int m = 0; m < 2; m++)
#pragma unroll
            for (int n = 0; n < 4; n++)
#pragma unroll
                for (int q = 0; q < 4; q++) acc[m][n][q] = 0.f;

        const uint32_t* xrow0 = xb + (mq * 32 + g) * XSTR + t;
        const uint32_t* wrow0 = wp + (nq * 32 + g) * XSTR + t;

#pragma unroll 2
        for (int kc = 0; kc < 16; kc++) {
            const int ko = kc * 8;
            uint32_t b[4][2];
#pragma unroll
            for (int n = 0; n < 4; n++) {
                b[n][0] = wrow0[n * (8 * XSTR) + ko];
                b[n][1] = wrow0[n * (8 * XSTR) + ko + 4];
            }
#pragma unroll
            for (int m = 0; m < 2; m++) {
                uint32_t a[4];
                const uint32_t* xr = xrow0 + m * (16 * XSTR);
                a[0] = xr[ko];
                a[1] = xr[8 * XSTR + ko];
                a[2] = xr[ko + 4];
                a[3] = xr[8 * XSTR + ko + 4];
#pragma unroll
                for (int n = 0; n < 4; n++) mma_bf16(acc[m][n], a, b[n]);
            }
        }

        // ---- (c) fold relu * fc_w -> per-row partials ----
#pragma unroll
        for (int m = 0; m < 2; m++) {
            float p0 = 0.f, p1 = 0.f;
#pragma unroll
            for (int n = 0; n < 4; n++) {
                const int col = nq * 32 + n * 8 + 2 * t;
                const float f0 = fcs[col], f1 = fcs[col + 1];
                p0 = fmaf(f0, fmaxf(acc[m][n][0], 0.f), p0);
                p0 = fmaf(f1, fmaxf(acc[m][n][1], 0.f), p0);
                p1 = fmaf(f0, fmaxf(acc[m][n][2], 0.f), p1);
                p1 = fmaf(f1, fmaxf(acc[m][n][3], 0.f), p1);
            }
            p0 += __shfl_xor_sync(0xffffffffu, p0, 1);
            p0 += __shfl_xor_sync(0xffffffffu, p0, 2);
            p1 += __shfl_xor_sync(0xffffffffu, p1, 1);
            p1 += __shfl_xor_sync(0xffffffffu, p1, 2);
            if (t == 0) {
                const int row = mq * 32 + m * 16 + g;
                atomicAdd(oac + row, p0);
                atomicAdd(oac + row + 8, p1);
            }
        }
        __syncthreads();   // partials + next-slot gather stores complete

        // ---- (d) finalize 128 rows ----
        if (tid < MTILE) {
            const int eo = tile * MTILE + tid;
            if (eo < batch) {
                const int* ris = reinterpret_cast<int*>(smu + RIS_W) + cur * 128;
                const int* tis = reinterpret_cast<int*>(smu + TIS_W) + cur * 128;
                float sum = fcb + oac[tid];
                const float* rap = ra_tab + (size_t)ris[tid] * CDIM;
                const float* tbp = tb_tab + (size_t)tis[tid] * CDIM;
                float rav[CDIM], tbv[CDIM];
#pragma unroll
                for (int q = 0; q < CDIM; q++) { rav[q] = __ldg(rap + q); tbv[q] = __ldg(tbp + q); }
#pragma unroll
                for (int i = 0; i < CDIM; i++)
#pragma unroll
                    for (int j = 0; j < CDIM; j++) {
                        const float x  = fmaf(rav[i], tbv[j], bia[CDIM * i + j]);
                        const float sg = 1.0f / (1.0f + __expf(-x));
                        sum = fmaf(fci[CDIM * i + j], sg, sum);
                    }
                out[eo] = sum;
            }
            oac[tid] = 0.f;
        }
        __syncthreads();   // oac reset visible before next tile's atomics
    }
}

// ---------------------------------------------------------------------------
extern "C" void kernel_launch(void* const* d_in, const int* in_sizes, int n_in,
                              void* d_out, int out_size)
{
    const int*   route_idx   = (const int*)  d_in[0];
    const int*   time_idx    = (const int*)  d_in[1];
    const float* route_table = (const float*)d_in[2];
    const float* time_table  = (const float*)d_in[3];
    const float* w           = (const float*)d_in[4];
    const float* mode_a      = (const float*)d_in[5];
    const float* mode_b      = (const float*)d_in[6];
    const float* mode_bias   = (const float*)d_in[7];
    const float* fc_w        = (const float*)d_in[8];
    const float* fc_b        = (const float*)d_in[9];
    float*       out         = (float*)d_out;

    const int batch    = in_sizes[0];
    const int n_routes = in_sizes[2] / DIM;
    const int n_time   = in_sizes[3] / DIM;

    float *ra_ptr = nullptr, *tb_ptr = nullptr;
    cudaGetSymbolAddress((void**)&ra_ptr, g_ra);
    cudaGetSymbolAddress((void**)&tb_ptr, g_tb);

    {
        const int total = n_routes + n_time;
        proj_fused<<<(total + 7) / 8, 256>>>(route_table, time_table, mode_a, mode_b,
                                             ra_ptr, tb_ptr, n_routes, n_time);
    }

    const int ntiles = (batch + MTILE - 1) / MTILE;
    const int smem_bytes = SM_WORDS * 4;   // ~206 KB
    cudaFuncSetAttribute(main_kernel, cudaFuncAttributeMaxDynamicSharedMemorySize, smem_bytes);

    int grid = 148;
    if (grid > ntiles) grid = ntiles;
    main_kernel<<<grid, 512, smem_bytes>>>(route_idx, time_idx, route_table, time_table,
                                           w, fc_w, fc_b, mode_bias,
                                           ra_ptr, tb_ptr, out, batch, ntiles);
}

// round 7
// speedup vs baseline: 5.9195x; 1.1029x over previous
#include <cuda_runtime.h>
#include <cuda_bf16.h>
#include <cstdint>

// ===========================================================================
// RouteNTMMatrix via bf16 mma.sync.m16n8k16, bf16-converted tables,
// batched coalesced gather, smem-prefetched epilogue.
//   gcp[b,k] = relu( sum_d (r[b,d]*t[b,d]) * w[d,k] ),  D=256, K=100 (pad 128)
//   out[b] = fc_b + fc_w[0:100].gcp + sum_ij fc_w[100+5i+j]*sigmoid(ra_i*tb_j+bias_ij)
// ===========================================================================

#define DIM    256
#define KOUT   100
#define MTILE  128
#define CDIM   5
#define XSTR   132            // x/w row stride in uint32 (bf16x2); 132%32=4 -> conflict-free frags

// word offsets in dynamic smem
#define WP_W   0                          // w bf16-pairs [128n][132]
#define XB_W   (WP_W + 128 * XSTR)        // x bf16-pairs, 2 slots [128][132]
#define FCS_W  (XB_W + 2 * 128 * XSTR)    // fc_w[0:100] padded 128
#define FCI_W  (FCS_W + 128)              // 25 interaction weights
#define BIA_W  (FCI_W + 32)               // 25 biases
#define OAC_W  (BIA_W + 32)               // per-row partials [128]
#define RV5_W  (OAC_W + 128)              // prefetched ra, 2 slots [128][5]
#define TV5_W  (RV5_W + 2 * 128 * CDIM)   // prefetched tb, 2 slots [128][5]
#define SM_WORDS (TV5_W + 2 * 128 * CDIM) // ~212 KB

__device__ float g_ra[100000 * CDIM];
__device__ float g_tb[2048   * CDIM];
__device__ __nv_bfloat16 g_rtb[100000 * DIM];   // route table, bf16
__device__ __nv_bfloat16 g_ttb[2048   * DIM];   // time table, bf16

__device__ __forceinline__ uint32_t pack_bf16(float lo, float hi) {
    uint32_t u;
    asm("cvt.rn.bf16x2.f32 %0, %1, %2;" : "=r"(u) : "f"(hi), "f"(lo));
    return u;
}
__device__ __forceinline__ void mma_bf16(float* d, const uint32_t* a, const uint32_t* b) {
    asm volatile("mma.sync.aligned.m16n8k16.row.col.f32.bf16.bf16.f32 "
                 "{%0,%1,%2,%3}, {%4,%5,%6,%7}, {%8,%9}, {%0,%1,%2,%3};"
                 : "+f"(d[0]), "+f"(d[1]), "+f"(d[2]), "+f"(d[3])
                 : "r"(a[0]), "r"(a[1]), "r"(a[2]), "r"(a[3]), "r"(b[0]), "r"(b[1]));
}
// elementwise bf16x2 product of two uint4 (8 bf16 lanes)
__device__ __forceinline__ uint4 hmul8(uint4 a, uint4 b) {
    const __nv_bfloat162* pa = reinterpret_cast<const __nv_bfloat162*>(&a);
    const __nv_bfloat162* pb = reinterpret_cast<const __nv_bfloat162*>(&b);
    __nv_bfloat162 x0 = __hmul2(pa[0], pb[0]);
    __nv_bfloat162 x1 = __hmul2(pa[1], pb[1]);
    __nv_bfloat162 x2 = __hmul2(pa[2], pb[2]);
    __nv_bfloat162 x3 = __hmul2(pa[3], pb[3]);
    uint4 r;
    r.x = *reinterpret_cast<uint32_t*>(&x0);
    r.y = *reinterpret_cast<uint32_t*>(&x1);
    r.z = *reinterpret_cast<uint32_t*>(&x2);
    r.w = *reinterpret_cast<uint32_t*>(&x3);
    return r;
}

// ---------------------------------------------------------------------------
// proj + convert: warp per row. Computes ra/tb projections AND writes the
// bf16 copy of the table row.
// ---------------------------------------------------------------------------
__global__ __launch_bounds__(256)
void proj_conv(const float* __restrict__ route_table,
               const float* __restrict__ time_table,
               const float* __restrict__ mode_a,
               const float* __restrict__ mode_b,
               float* __restrict__ ra_tab, float* __restrict__ tb_tab,
               __nv_bfloat16* __restrict__ rtb, __nv_bfloat16* __restrict__ ttb,
               int n_routes, int n_time)
{
    __shared__ float sA[DIM * CDIM];
    __shared__ float sB[DIM * CDIM];
    const int tid = threadIdx.x;
    for (int i = tid; i < DIM * CDIM; i += 256) { sA[i] = mode_a[i]; sB[i] = mode_b[i]; }
    __syncthreads();

    const int gwarp = (blockIdx.x * 256 + tid) >> 5;
    const int lane  = tid & 31;
    if (gwarp >= n_routes + n_time) return;

    const bool is_r = gwarp < n_routes;
    const int  lrow = is_r ? gwarp : (gwarp - n_routes);
    const float* rowf = (is_r ? route_table : time_table) + (size_t)lrow * DIM;
    const float* P = is_r ? sA : sB;

    // ---- bf16 conversion (vectorized) ----
    const float4* r4 = reinterpret_cast<const float4*>(rowf);
    const float4 v0 = __ldg(r4 + lane);
    const float4 v1 = __ldg(r4 + 32 + lane);
    uint2* brow = reinterpret_cast<uint2*>((is_r ? rtb : ttb) + (size_t)lrow * DIM);
    brow[lane]      = make_uint2(pack_bf16(v0.x, v0.y), pack_bf16(v0.z, v0.w));
    brow[lane + 32] = make_uint2(pack_bf16(v1.x, v1.y), pack_bf16(v1.z, v1.w));

    // ---- projection (scalar, conflict-free stride-5 smem) ----
    float v[DIM / 32];
#pragma unroll
    for (int it = 0; it < DIM / 32; it++) v[it] = __ldg(rowf + lane + 32 * it);

    float acc[CDIM] = {0.f, 0.f, 0.f, 0.f, 0.f};
#pragma unroll
    for (int it = 0; it < DIM / 32; it++) {
        const float* pc = P + (lane + 32 * it) * CDIM;
#pragma unroll
        for (int c = 0; c < CDIM; c++) acc[c] = fmaf(v[it], pc[c], acc[c]);
    }
#pragma unroll
    for (int off = 16; off; off >>= 1)
#pragma unroll
        for (int c = 0; c < CDIM; c++) acc[c] += __shfl_xor_sync(0xffffffffu, acc[c], off);

    if (lane == 0) {
        float* o = (is_r ? ra_tab : tb_tab) + (size_t)lrow * CDIM;
#pragma unroll
        for (int c = 0; c < CDIM; c++) o[c] = acc[c];
    }
}

// ---------------------------------------------------------------------------
// Gather one tile (bf16 tables): warp owns 8 rows; 16 LDG.128 batched up
// front, then hmul + STS.128. Also prefetches epilogue ra/tb into smem.
// ---------------------------------------------------------------------------
__device__ __forceinline__ void gather_tile(
    uint32_t* smu, int slot, int tile,
    const int* __restrict__ route_idx, const int* __restrict__ time_idx,
    const uint4* __restrict__ RTB, const uint4* __restrict__ TTB,
    const float* __restrict__ ra_tab, const float* __restrict__ tb_tab,
    int batch, int wid, int lane)
{
    uint32_t* xb  = smu + XB_W + slot * (128 * XSTR);
    float*    rv5 = reinterpret_cast<float*>(smu + RV5_W) + slot * (128 * CDIM);
    float*    tv5 = reinterpret_cast<float*>(smu + TV5_W) + slot * (128 * CDIM);

    const int li  = lane & 7;
    const int row = wid * 8 + li;
    const int ei  = min(tile * MTILE + row, batch - 1);
    const int ridx = __ldg(route_idx + ei);
    const int tidx = __ldg(time_idx  + ei);

    // batched row loads: 16 independent LDG.128 in flight per thread
    uint4 rr[8], tt[8];
#pragma unroll
    for (int i = 0; i < 8; i++) {
        const int r0 = __shfl_sync(0xffffffffu, ridx, i);
        const int t0 = __shfl_sync(0xffffffffu, tidx, i);
        rr[i] = __ldg(RTB + (size_t)r0 * 32 + lane);
        tt[i] = __ldg(TTB + (size_t)t0 * 32 + lane);
    }

    // epilogue prefetch: 5+5 floats per row into smem
    if (lane < 8) {
#pragma unroll
        for (int c = 0; c < CDIM; c++) {
            rv5[row * CDIM + c] = __ldg(ra_tab + (size_t)ridx * CDIM + c);
            tv5[row * CDIM + c] = __ldg(tb_tab + (size_t)tidx * CDIM + c);
        }
    }

    // multiply + store (lane covers bf16x2 words 4*lane..4*lane+3 of each row)
#pragma unroll
    for (int i = 0; i < 8; i++) {
        *reinterpret_cast<uint4*>(xb + (wid * 8 + i) * XSTR + 4 * lane) = hmul8(rr[i], tt[i]);
    }
}

// ---------------------------------------------------------------------------
// Main persistent kernel: 512 threads (16 warps), tile = 128 rows,
// double-buffered x, 2 barriers/tile.
// ---------------------------------------------------------------------------
__global__ __launch_bounds__(512, 1)
void main_kernel(const int*   __restrict__ route_idx,
                 const int*   __restrict__ time_idx,
                 const uint4* __restrict__ RTB,        // bf16 route table
                 const uint4* __restrict__ TTB,        // bf16 time table
                 const float* __restrict__ w,          // [256][100]
                 const float* __restrict__ fc_w,       // [125]
                 const float* __restrict__ fc_b,       // [1]
                 const float* __restrict__ mode_bias,  // [25]
                 const float* __restrict__ ra_tab,
                 const float* __restrict__ tb_tab,
                 float*       __restrict__ out,
                 int batch, int ntiles)
{
    extern __shared__ uint32_t smu[];
    uint32_t* wp  = smu + WP_W;
    float*    fcs = reinterpret_cast<float*>(smu + FCS_W);
    float*    fci = reinterpret_cast<float*>(smu + FCI_W);
    float*    bia = reinterpret_cast<float*>(smu + BIA_W);
    float*    oac = reinterpret_cast<float*>(smu + OAC_W);

    const int tid  = threadIdx.x;
    const int wid  = tid >> 5;
    const int lane = tid & 31;

    // ---- stage w as bf16 pairs: wp[n*XSTR + kp] = {bf16(w[2kp][n]), bf16(w[2kp+1][n])} ----
    for (int i = tid; i < 128 * 128; i += 512) {
        const int n = i & 127, kp = i >> 7;
        const float f0 = (n < KOUT) ? __ldg(w + (2 * kp)     * KOUT + n) : 0.f;
        const float f1 = (n < KOUT) ? __ldg(w + (2 * kp + 1) * KOUT + n) : 0.f;
        wp[n * XSTR + kp] = pack_bf16(f0, f1);
    }
    if (tid < 128)                 fcs[tid] = (tid < KOUT) ? __ldg(fc_w + tid) : 0.f;
    if (tid >= 128 && tid < 153)   fci[tid - 128] = __ldg(fc_w + KOUT + tid - 128);
    if (tid >= 160 && tid < 185)   bia[tid - 160] = __ldg(mode_bias + tid - 160);
    if (tid < 128)                 oac[tid] = 0.f;

    const float fcb = __ldg(fc_b);

    // mma mapping: warp = (mq, nq); fragment lane = (g, t)
    const int mq = wid >> 2, nq = wid & 3;
    const int g  = lane >> 2, t = lane & 3;

    const int grid = gridDim.x;

    // prologue: gather first tile into slot 0 (also covered by following barrier)
    gather_tile(smu, 0, blockIdx.x, route_idx, time_idx, RTB, TTB,
                ra_tab, tb_tab, batch, wid, lane);
    __syncthreads();

    int it = 0;
    for (int tile = blockIdx.x; tile < ntiles; tile += grid, it++) {
        const int cur = it & 1;
        uint32_t* xb = smu + XB_W + cur * (128 * XSTR);

        // ---- (a) gather next tile into other slot ----
        if (tile + grid < ntiles)
            gather_tile(smu, cur ^ 1, tile + grid, route_idx, time_idx, RTB, TTB,
                        ra_tab, tb_tab, batch, wid, lane);

        // ---- (b) mma over K: 16 chunks of k16 ----
        float acc[2][4][4];
#pragma unroll
        for (int m = 0; m < 2; m++)
#pragma unroll
            for (int n = 0; n < 4; n++)
#pragma unroll
                for (int q = 0; q < 4; q++) acc[m][n][q] = 0.f;

        const uint32_t* xrow0 = xb + (mq * 32 + g) * XSTR + t;
        const uint32_t* wrow0 = wp + (nq * 32 + g) * XSTR + t;

#pragma unroll 2
        for (int kc = 0; kc < 16; kc++) {
            const int ko = kc * 8;
            uint32_t b[4][2];
#pragma unroll
            for (int n = 0; n < 4; n++) {
                b[n][0] = wrow0[n * (8 * XSTR) + ko];
                b[n][1] = wrow0[n * (8 * XSTR) + ko + 4];
            }
#pragma unroll
            for (int m = 0; m < 2; m++) {
                uint32_t a[4];
                const uint32_t* xr = xrow0 + m * (16 * XSTR);
                a[0] = xr[ko];
                a[1] = xr[8 * XSTR + ko];
                a[2] = xr[ko + 4];
                a[3] = xr[8 * XSTR + ko + 4];
#pragma unroll
                for (int n = 0; n < 4; n++) mma_bf16(acc[m][n], a, b[n]);
            }
        }

        // ---- (c) fold relu * fc_w -> per-row partials ----
#pragma unroll
        for (int m = 0; m < 2; m++) {
            float p0 = 0.f, p1 = 0.f;
#pragma unroll
            for (int n = 0; n < 4; n++) {
                const int col = nq * 32 + n * 8 + 2 * t;
                const float f0 = fcs[col], f1 = fcs[col + 1];
                p0 = fmaf(f0, fmaxf(acc[m][n][0], 0.f), p0);
                p0 = fmaf(f1, fmaxf(acc[m][n][1], 0.f), p0);
                p1 = fmaf(f0, fmaxf(acc[m][n][2], 0.f), p1);
                p1 = fmaf(f1, fmaxf(acc[m][n][3], 0.f), p1);
            }
            p0 += __shfl_xor_sync(0xffffffffu, p0, 1);
            p0 += __shfl_xor_sync(0xffffffffu, p0, 2);
            p1 += __shfl_xor_sync(0xffffffffu, p1, 1);
            p1 += __shfl_xor_sync(0xffffffffu, p1, 2);
            if (t == 0) {
                const int row = mq * 32 + m * 16 + g;
                atomicAdd(oac + row, p0);
                atomicAdd(oac + row + 8, p1);
            }
        }
        __syncthreads();   // partials + next-slot gather stores complete

        // ---- (d) finalize 128 rows (pure smem epilogue) ----
        if (tid < MTILE) {
            const int eo = tile * MTILE + tid;
            if (eo < batch) {
                const float* rv5 = reinterpret_cast<float*>(smu + RV5_W) + cur * (128 * CDIM);
                const float* tv5 = reinterpret_cast<float*>(smu + TV5_W) + cur * (128 * CDIM);
                float sum = fcb + oac[tid];
                float rav[CDIM], tbv[CDIM];
#pragma unroll
                for (int q = 0; q < CDIM; q++) {
                    rav[q] = rv5[tid * CDIM + q];
                    tbv[q] = tv5[tid * CDIM + q];
                }
#pragma unroll
                for (int i = 0; i < CDIM; i++)
#pragma unroll
                    for (int j = 0; j < CDIM; j++) {
                        const float x  = fmaf(rav[i], tbv[j], bia[CDIM * i + j]);
                        const float sg = 1.0f / (1.0f + __expf(-x));
                        sum = fmaf(fci[CDIM * i + j], sg, sum);
                    }
                out[eo] = sum;
            }
            oac[tid] = 0.f;
        }
        __syncthreads();   // oac reset + rv5 slot reuse ordering
    }
}

// ---------------------------------------------------------------------------
extern "C" void kernel_launch(void* const* d_in, const int* in_sizes, int n_in,
                              void* d_out, int out_size)
{
    const int*   route_idx   = (const int*)  d_in[0];
    const int*   time_idx    = (const int*)  d_in[1];
    const float* route_table = (const float*)d_in[2];
    const float* time_table  = (const float*)d_in[3];
    const float* w           = (const float*)d_in[4];
    const float* mode_a      = (const float*)d_in[5];
    const float* mode_b      = (const float*)d_in[6];
    const float* mode_bias   = (const float*)d_in[7];
    const float* fc_w        = (const float*)d_in[8];
    const float* fc_b        = (const float*)d_in[9];
    float*       out         = (float*)d_out;

    const int batch    = in_sizes[0];
    const int n_routes = in_sizes[2] / DIM;
    const int n_time   = in_sizes[3] / DIM;

    float *ra_ptr = nullptr, *tb_ptr = nullptr;
    __nv_bfloat16 *rtb_ptr = nullptr, *ttb_ptr = nullptr;
    cudaGetSymbolAddress((void**)&ra_ptr,  g_ra);
    cudaGetSymbolAddress((void**)&tb_ptr,  g_tb);
    cudaGetSymbolAddress((void**)&rtb_ptr, g_rtb);
    cudaGetSymbolAddress((void**)&ttb_ptr, g_ttb);

    {
        const int total = n_routes + n_time;
        proj_conv<<<(total + 7) / 8, 256>>>(route_table, time_table, mode_a, mode_b,
                                            ra_ptr, tb_ptr, rtb_ptr, ttb_ptr,
                                            n_routes, n_time);
    }

    const int ntiles = (batch + MTILE - 1) / MTILE;
    const int smem_bytes = SM_WORDS * 4;   // ~212 KB
    cudaFuncSetAttribute(main_kernel, cudaFuncAttributeMaxDynamicSharedMemorySize, smem_bytes);

    int grid = 148;
    if (grid > ntiles) grid = ntiles;
    main_kernel<<<grid, 512, smem_bytes>>>(route_idx, time_idx,
                                           (const uint4*)rtb_ptr, (const uint4*)ttb_ptr,
                                           w, fc_w, fc_b, mode_bias,
                                           ra_ptr, tb_ptr, out, batch, ntiles);
}

// round 8
// speedup vs baseline: 6.2638x; 1.0582x over previous
#include <cuda_runtime.h>
#include <cuda_bf16.h>
#include <cstdint>

// ===========================================================================
// RouteNTMMatrix: bf16 mma.sync + ldmatrix, staggered gather/MMA overlap.
//   gcp[b,k] = relu( sum_d (r[b,d]*t[b,d]) * w[d,k] ),  D=256, K=100 (pad 128)
//   out[b] = fc_b + fc_w[0:100].gcp + sum_ij fc_w[100+5i+j]*sigmoid(ra_i*tb_j+bias_ij)
// ===========================================================================

#define DIM    256
#define KOUT   100
#define MTILE  128
#define CDIM   5
#define XSTR   132            // x/w row stride in uint32 (bf16x2); 132%32=4 -> LDSM conflict-free

// word offsets in dynamic smem
#define WP_W   0                          // w bf16-pairs [128n][132]
#define XB_W   (WP_W + 128 * XSTR)        // x bf16-pairs, 2 slots [128][132]
#define FCS_W  (XB_W + 2 * 128 * XSTR)    // fc_w[0:100] padded 128
#define FCI_W  (FCS_W + 128)              // 25 interaction weights
#define BIA_W  (FCI_W + 32)               // 25 biases
#define OAC_W  (BIA_W + 32)               // per-row partials [128]
#define RV5_W  (OAC_W + 128)              // prefetched ra, 2 slots [128][5]
#define TV5_W  (RV5_W + 2 * 128 * CDIM)   // prefetched tb, 2 slots [128][5]
#define SM_WORDS (TV5_W + 2 * 128 * CDIM) // ~212 KB

__device__ float g_ra[100000 * CDIM];
__device__ float g_tb[2048   * CDIM];
__device__ __nv_bfloat16 g_rtb[100000 * DIM];   // route table, bf16
__device__ __nv_bfloat16 g_ttb[2048   * DIM];   // time table, bf16

__device__ __forceinline__ uint32_t pack_bf16(float lo, float hi) {
    uint32_t u;
    asm("cvt.rn.bf16x2.f32 %0, %1, %2;" : "=r"(u) : "f"(hi), "f"(lo));
    return u;
}
__device__ __forceinline__ void mma_bf16(float* d, const uint32_t* a,
                                         uint32_t b0, uint32_t b1) {
    asm volatile("mma.sync.aligned.m16n8k16.row.col.f32.bf16.bf16.f32 "
                 "{%0,%1,%2,%3}, {%4,%5,%6,%7}, {%8,%9}, {%0,%1,%2,%3};"
                 : "+f"(d[0]), "+f"(d[1]), "+f"(d[2]), "+f"(d[3])
                 : "r"(a[0]), "r"(a[1]), "r"(a[2]), "r"(a[3]), "r"(b0), "r"(b1));
}
#define LDSM_X4(r0, r1, r2, r3, addr) \
    asm volatile("ldmatrix.sync.aligned.m8n8.x4.shared.b16 {%0,%1,%2,%3}, [%4];" \
                 : "=r"(r0), "=r"(r1), "=r"(r2), "=r"(r3) : "r"(addr))

__device__ __forceinline__ uint32_t smem_u32(const void* p) {
    uint32_t a;
    asm("{ .reg .u64 t; cvta.to.shared.u64 t, %1; cvt.u32.u64 %0, t; }" : "=r"(a) : "l"(p));
    return a;
}
__device__ __forceinline__ uint4 hmul8(uint4 a, uint4 b) {
    const __nv_bfloat162* pa = reinterpret_cast<const __nv_bfloat162*>(&a);
    const __nv_bfloat162* pb = reinterpret_cast<const __nv_bfloat162*>(&b);
    __nv_bfloat162 x0 = __hmul2(pa[0], pb[0]);
    __nv_bfloat162 x1 = __hmul2(pa[1], pb[1]);
    __nv_bfloat162 x2 = __hmul2(pa[2], pb[2]);
    __nv_bfloat162 x3 = __hmul2(pa[3], pb[3]);
    uint4 r;
    r.x = *reinterpret_cast<uint32_t*>(&x0);
    r.y = *reinterpret_cast<uint32_t*>(&x1);
    r.z = *reinterpret_cast<uint32_t*>(&x2);
    r.w = *reinterpret_cast<uint32_t*>(&x3);
    return r;
}

// ---------------------------------------------------------------------------
// proj + convert: warp per row. Single vectorized read of the row feeds both
// the projection and the bf16 conversion.
// Pt layout: [c][h][j][lane], value = mode[(h*128 + 4*lane + j)*5 + c]
// ---------------------------------------------------------------------------
__global__ __launch_bounds__(256)
void proj_conv(const float* __restrict__ route_table,
               const float* __restrict__ time_table,
               const float* __restrict__ mode_a,
               const float* __restrict__ mode_b,
               float* __restrict__ ra_tab, float* __restrict__ tb_tab,
               __nv_bfloat16* __restrict__ rtb, __nv_bfloat16* __restrict__ ttb,
               int n_routes, int n_time)
{
    __shared__ float PtA[CDIM * 2 * 4 * 32];   // 1280 words
    __shared__ float PtB[CDIM * 2 * 4 * 32];
    const int tid = threadIdx.x;
    for (int i = tid; i < CDIM * 2 * 4 * 32; i += 256) {
        const int ln = i & 31, j = (i >> 5) & 3, h = (i >> 7) & 1, c = i >> 8;
        const int d = h * 128 + 4 * ln + j;
        PtA[i] = __ldg(mode_a + d * CDIM + c);
        PtB[i] = __ldg(mode_b + d * CDIM + c);
    }
    __syncthreads();

    const int gwarp = (blockIdx.x * 256 + tid) >> 5;
    const int lane  = tid & 31;
    if (gwarp >= n_routes + n_time) return;

    const bool is_r = gwarp < n_routes;
    const int  lrow = is_r ? gwarp : (gwarp - n_routes);
    const float* rowf = (is_r ? route_table : time_table) + (size_t)lrow * DIM;
    const float* Pt = is_r ? PtA : PtB;

    const float4* r4 = reinterpret_cast<const float4*>(rowf);
    const float4 v0 = __ldg(r4 + lane);        // d = 4*lane + j
    const float4 v1 = __ldg(r4 + 32 + lane);   // d = 128 + 4*lane + j

    // bf16 conversion
    uint2* brow = reinterpret_cast<uint2*>((is_r ? rtb : ttb) + (size_t)lrow * DIM);
    brow[lane]      = make_uint2(pack_bf16(v0.x, v0.y), pack_bf16(v0.z, v0.w));
    brow[lane + 32] = make_uint2(pack_bf16(v1.x, v1.y), pack_bf16(v1.z, v1.w));

    // projection (conflict-free LDS: lane stride 1)
    const float vv[2][4] = {{v0.x, v0.y, v0.z, v0.w}, {v1.x, v1.y, v1.z, v1.w}};
    float acc[CDIM] = {0.f, 0.f, 0.f, 0.f, 0.f};
#pragma unroll
    for (int c = 0; c < CDIM; c++)
#pragma unroll
        for (int h = 0; h < 2; h++)
#pragma unroll
            for (int j = 0; j < 4; j++)
                acc[c] = fmaf(vv[h][j], Pt[((c * 2 + h) * 4 + j) * 32 + lane], acc[c]);

#pragma unroll
    for (int off = 16; off; off >>= 1)
#pragma unroll
        for (int c = 0; c < CDIM; c++) acc[c] += __shfl_xor_sync(0xffffffffu, acc[c], off);

    if (lane == 0) {
        float* o = (is_r ? ra_tab : tb_tab) + (size_t)lrow * CDIM;
#pragma unroll
        for (int c = 0; c < CDIM; c++) o[c] = acc[c];
    }
}

// ---------------------------------------------------------------------------
// Gather one tile (bf16 tables): warp owns 8 rows; 16 batched LDG.128,
// hmul + STS.128; prefetches epilogue ra/tb into smem.
// ---------------------------------------------------------------------------
__device__ __forceinline__ void gather_tile(
    uint32_t* smu, int slot, int tile,
    const int* __restrict__ route_idx, const int* __restrict__ time_idx,
    const uint4* __restrict__ RTB, const uint4* __restrict__ TTB,
    const float* __restrict__ ra_tab, const float* __restrict__ tb_tab,
    int batch, int wid, int lane)
{
    uint32_t* xb  = smu + XB_W + slot * (128 * XSTR);
    float*    rv5 = reinterpret_cast<float*>(smu + RV5_W) + slot * (128 * CDIM);
    float*    tv5 = reinterpret_cast<float*>(smu + TV5_W) + slot * (128 * CDIM);

    const int li  = lane & 7;
    const int row = wid * 8 + li;
    const int ei  = min(tile * MTILE + row, batch - 1);
    const int ridx = __ldg(route_idx + ei);
    const int tidx = __ldg(time_idx  + ei);

    uint4 rr[8], tt[8];
#pragma unroll
    for (int i = 0; i < 8; i++) {
        const int r0 = __shfl_sync(0xffffffffu, ridx, i);
        const int t0 = __shfl_sync(0xffffffffu, tidx, i);
        rr[i] = __ldg(RTB + (size_t)r0 * 32 + lane);
        tt[i] = __ldg(TTB + (size_t)t0 * 32 + lane);
    }

    if (lane < 8) {
#pragma unroll
        for (int c = 0; c < CDIM; c++) {
            rv5[row * CDIM + c] = __ldg(ra_tab + (size_t)ridx * CDIM + c);
            tv5[row * CDIM + c] = __ldg(tb_tab + (size_t)tidx * CDIM + c);
        }
    }

#pragma unroll
    for (int i = 0; i < 8; i++)
        *reinterpret_cast<uint4*>(xb + (wid * 8 + i) * XSTR + 4 * lane) = hmul8(rr[i], tt[i]);
}

// ---------------------------------------------------------------------------
// Main persistent kernel: 512 threads; warps 0-7 gather->mma, 8-15 mma->gather.
// ---------------------------------------------------------------------------
__global__ __launch_bounds__(512, 1)
void main_kernel(const int*   __restrict__ route_idx,
                 const int*   __restrict__ time_idx,
                 const uint4* __restrict__ RTB,
                 const uint4* __restrict__ TTB,
                 const float* __restrict__ w,
                 const float* __restrict__ fc_w,
                 const float* __restrict__ fc_b,
                 const float* __restrict__ mode_bias,
                 const float* __restrict__ ra_tab,
                 const float* __restrict__ tb_tab,
                 float*       __restrict__ out,
                 int batch, int ntiles)
{
    extern __shared__ uint32_t smu[];
    uint32_t* wp  = smu + WP_W;
    float*    fcs = reinterpret_cast<float*>(smu + FCS_W);
    float*    fci = reinterpret_cast<float*>(smu + FCI_W);
    float*    bia = reinterpret_cast<float*>(smu + BIA_W);
    float*    oac = reinterpret_cast<float*>(smu + OAC_W);

    const int tid  = threadIdx.x;
    const int wid  = tid >> 5;
    const int lane = tid & 31;
    const uint32_t sm_u32 = smem_u32(smu);

    // stage w bf16-pairs: wp[n*XSTR + kp] = {bf16(w[2kp][n]), bf16(w[2kp+1][n])}
    for (int i = tid; i < 128 * 128; i += 512) {
        const int n = i & 127, kp = i >> 7;
        const float f0 = (n < KOUT) ? __ldg(w + (2 * kp)     * KOUT + n) : 0.f;
        const float f1 = (n < KOUT) ? __ldg(w + (2 * kp + 1) * KOUT + n) : 0.f;
        wp[n * XSTR + kp] = pack_bf16(f0, f1);
    }
    if (tid < 128)                 fcs[tid] = (tid < KOUT) ? __ldg(fc_w + tid) : 0.f;
    if (tid >= 128 && tid < 153)   fci[tid - 128] = __ldg(fc_w + KOUT + tid - 128);
    if (tid >= 160 && tid < 185)   bia[tid - 160] = __ldg(mode_bias + tid - 160);
    if (tid < 128)                 oac[tid] = 0.f;

    const float fcb = __ldg(fc_b);

    const int mq = wid >> 2, nq = wid & 3;   // warp tile: rows mq*32+{0,16}, cols nq*32
    const int t  = lane & 3;

    // ldmatrix thread-address components
    const int a_row   = (lane & 7) + ((lane >> 3) & 1) * 8;   // row within 16
    const int a_khalf = (lane >> 4) * 4;                      // k-half in words
    const int b_n     = ((lane >> 4) << 3) + (lane & 7);      // n within 16 (2 tiles)
    const int b_khalf = ((lane >> 3) & 1) * 4;

    // B addresses are slot-independent
    uint32_t bAddr[2];
#pragma unroll
    for (int p = 0; p < 2; p++)
        bAddr[p] = sm_u32 + ((WP_W) + (nq * 32 + p * 16 + b_n) * XSTR + b_khalf) * 4;

    const int grid = gridDim.x;
    const bool early = (wid < 8);   // gather before mma

    gather_tile(smu, 0, blockIdx.x, route_idx, time_idx, RTB, TTB,
                ra_tab, tb_tab, batch, wid, lane);
    __syncthreads();

    int it = 0;
    for (int tile = blockIdx.x; tile < ntiles; tile += grid, it++) {
        const int cur = it & 1;
        const bool have_next = (tile + grid < ntiles);

        if (early && have_next)
            gather_tile(smu, cur ^ 1, tile + grid, route_idx, time_idx, RTB, TTB,
                        ra_tab, tb_tab, batch, wid, lane);

        // ---- mma over K via ldmatrix ----
        float acc[2][4][4];
#pragma unroll
        for (int m = 0; m < 2; m++)
#pragma unroll
            for (int n = 0; n < 4; n++)
#pragma unroll
                for (int q = 0; q < 4; q++) acc[m][n][q] = 0.f;

        uint32_t aAddr[2];
#pragma unroll
        for (int m = 0; m < 2; m++)
            aAddr[m] = sm_u32 + (XB_W + cur * (128 * XSTR)
                       + (mq * 32 + m * 16 + a_row) * XSTR + a_khalf) * 4;

#pragma unroll 2
        for (int kc = 0; kc < 16; kc++) {
            const uint32_t kb = kc * 32;   // 8 words * 4 bytes
            uint32_t bb[8];
            LDSM_X4(bb[0], bb[1], bb[2], bb[3], bAddr[0] + kb);
            LDSM_X4(bb[4], bb[5], bb[6], bb[7], bAddr[1] + kb);
#pragma unroll
            for (int m = 0; m < 2; m++) {
                uint32_t a[4];
                LDSM_X4(a[0], a[1], a[2], a[3], aAddr[m] + kb);
                mma_bf16(acc[m][0], a, bb[0], bb[1]);
                mma_bf16(acc[m][1], a, bb[2], bb[3]);
                mma_bf16(acc[m][2], a, bb[4], bb[5]);
                mma_bf16(acc[m][3], a, bb[6], bb[7]);
            }
        }

        // ---- fold relu * fc_w -> per-row partials ----
#pragma unroll
        for (int m = 0; m < 2; m++) {
            float p0 = 0.f, p1 = 0.f;
#pragma unroll
            for (int n = 0; n < 4; n++) {
                const int col = nq * 32 + n * 8 + 2 * t;
                const float f0 = fcs[col], f1 = fcs[col + 1];
                p0 = fmaf(f0, fmaxf(acc[m][n][0], 0.f), p0);
                p0 = fmaf(f1, fmaxf(acc[m][n][1], 0.f), p0);
                p1 = fmaf(f0, fmaxf(acc[m][n][2], 0.f), p1);
                p1 = fmaf(f1, fmaxf(acc[m][n][3], 0.f), p1);
            }
            p0 += __shfl_xor_sync(0xffffffffu, p0, 1);
            p0 += __shfl_xor_sync(0xffffffffu, p0, 2);
            p1 += __shfl_xor_sync(0xffffffffu, p1, 1);
            p1 += __shfl_xor_sync(0xffffffffu, p1, 2);
            if (t == 0) {
                const int row = mq * 32 + m * 16 + (lane >> 2);
                atomicAdd(oac + row, p0);
                atomicAdd(oac + row + 8, p1);
            }
        }

        if (!early && have_next)
            gather_tile(smu, cur ^ 1, tile + grid, route_idx, time_idx, RTB, TTB,
                        ra_tab, tb_tab, batch, wid, lane);

        __syncthreads();   // partials + slot^1 gather complete

        // ---- finalize 128 rows (pure smem epilogue) ----
        if (tid < MTILE) {
            const int eo = tile * MTILE + tid;
            if (eo < batch) {
                const float* rv5 = reinterpret_cast<float*>(smu + RV5_W) + cur * (128 * CDIM);
                const float* tv5 = reinterpret_cast<float*>(smu + TV5_W) + cur * (128 * CDIM);
                float sum = fcb + oac[tid];
                float rav[CDIM], tbv[CDIM];
#pragma unroll
                for (int q = 0; q < CDIM; q++) {
                    rav[q] = rv5[tid * CDIM + q];
                    tbv[q] = tv5[tid * CDIM + q];
                }
#pragma unroll
                for (int i = 0; i < CDIM; i++)
#pragma unroll
                    for (int j = 0; j < CDIM; j++) {
                        const float x  = fmaf(rav[i], tbv[j], bia[CDIM * i + j]);
                        const float sg = 1.0f / (1.0f + __expf(-x));
                        sum = fmaf(fci[CDIM * i + j], sg, sum);
                    }
                out[eo] = sum;
            }
            oac[tid] = 0.f;
        }
        __syncthreads();
    }
}

// ---------------------------------------------------------------------------
extern "C" void kernel_launch(void* const* d_in, const int* in_sizes, int n_in,
                              void* d_out, int out_size)
{
    const int*   route_idx   = (const int*)  d_in[0];
    const int*   time_idx    = (const int*)  d_in[1];
    const float* route_table = (const float*)d_in[2];
    const float* time_table  = (const float*)d_in[3];
    const float* w           = (const float*)d_in[4];
    const float* mode_a      = (const float*)d_in[5];
    const float* mode_b      = (const float*)d_in[6];
    const float* mode_bias   = (const float*)d_in[7];
    const float* fc_w        = (const float*)d_in[8];
    const float* fc_b        = (const float*)d_in[9];
    float*       out         = (float*)d_out;

    const int batch    = in_sizes[0];
    const int n_routes = in_sizes[2] / DIM;
    const int n_time   = in_sizes[3] / DIM;

    float *ra_ptr = nullptr, *tb_ptr = nullptr;
    __nv_bfloat16 *rtb_ptr = nullptr, *ttb_ptr = nullptr;
    cudaGetSymbolAddress((void**)&ra_ptr,  g_ra);
    cudaGetSymbolAddress((void**)&tb_ptr,  g_tb);
    cudaGetSymbolAddress((void**)&rtb_ptr, g_rtb);
    cudaGetSymbolAddress((void**)&ttb_ptr, g_ttb);

    {
        const int total = n_routes + n_time;
        proj_conv<<<(total + 7) / 8, 256>>>(route_table, time_table, mode_a, mode_b,
                                            ra_ptr, tb_ptr, rtb_ptr, ttb_ptr,
                                            n_routes, n_time);
    }

    const int ntiles = (batch + MTILE - 1) / MTILE;
    const int smem_bytes = SM_WORDS * 4;
    cudaFuncSetAttribute(main_kernel, cudaFuncAttributeMaxDynamicSharedMemorySize, smem_bytes);

    int grid = 148;
    if (grid > ntiles) grid = ntiles;
    main_kernel<<<grid, 512, smem_bytes>>>(route_idx, time_idx,
                                           (const uint4*)rtb_ptr, (const uint4*)ttb_ptr,
                                           w, fc_w, fc_b, mode_bias,
                                           ra_ptr, tb_ptr, out, batch, ntiles);
}

// round 9
// speedup vs baseline: 7.3046x; 1.1662x over previous
#include <cuda_runtime.h>
#include <cuda_bf16.h>
#include <cstdint>

// ===========================================================================
// RouteNTMMatrix: bf16 mma.sync + ldmatrix; two independent 256-thread
// pipelines per CTA (named barriers), 64-row tiles, load/compute interleave.
// ===========================================================================

#define DIM    256
#define KOUT   100
#define CDIM   5
#define XSTR   132            // row stride in uint32 (bf16x2); 132%32=4 -> LDSM conflict-free

// word offsets in dynamic smem
#define WP_W   0                            // w bf16-pairs [128n][132]
#define XB_W   (WP_W + 128 * XSTR)          // x tiles: 2 groups x 2 slots x [64][132]
#define FCS_W  (XB_W + 4 * 64 * XSTR)
#define FCI_W  (FCS_W + 128)
#define BIA_W  (FCI_W + 32)
#define OAC_W  (BIA_W + 32)                 // per-row partials, 2 groups x 64
#define RV5_W  (OAC_W + 128)                // ra prefetch: 2 groups x 2 slots x 64 x 5
#define TV5_W  (RV5_W + 4 * 64 * CDIM)
#define SM_WORDS (TV5_W + 4 * 64 * CDIM)    // 53568 words = 214272 B

__device__ float g_ra[100000 * CDIM];
__device__ float g_tb[2048   * CDIM];
__device__ __nv_bfloat16 g_rtb[100000 * DIM];
__device__ __nv_bfloat16 g_ttb[2048   * DIM];

__device__ __forceinline__ uint32_t pack_bf16(float lo, float hi) {
    uint32_t u;
    asm("cvt.rn.bf16x2.f32 %0, %1, %2;" : "=r"(u) : "f"(hi), "f"(lo));
    return u;
}
__device__ __forceinline__ void mma_bf16(float* d, const uint32_t* a,
                                         uint32_t b0, uint32_t b1) {
    asm volatile("mma.sync.aligned.m16n8k16.row.col.f32.bf16.bf16.f32 "
                 "{%0,%1,%2,%3}, {%4,%5,%6,%7}, {%8,%9}, {%0,%1,%2,%3};"
                 : "+f"(d[0]), "+f"(d[1]), "+f"(d[2]), "+f"(d[3])
                 : "r"(a[0]), "r"(a[1]), "r"(a[2]), "r"(a[3]), "r"(b0), "r"(b1));
}
#define LDSM_X4(r0, r1, r2, r3, addr) \
    asm volatile("ldmatrix.sync.aligned.m8n8.x4.shared.b16 {%0,%1,%2,%3}, [%4];" \
                 : "=r"(r0), "=r"(r1), "=r"(r2), "=r"(r3) : "r"(addr))
#define BARG(id) asm volatile("bar.sync %0, %1;" :: "r"(id), "r"(256) : "memory")

__device__ __forceinline__ uint32_t smem_u32(const void* p) {
    uint32_t a;
    asm("{ .reg .u64 t; cvta.to.shared.u64 t, %1; cvt.u32.u64 %0, t; }" : "=r"(a) : "l"(p));
    return a;
}
__device__ __forceinline__ uint4 hmul8(uint4 a, uint4 b) {
    const __nv_bfloat162* pa = reinterpret_cast<const __nv_bfloat162*>(&a);
    const __nv_bfloat162* pb = reinterpret_cast<const __nv_bfloat162*>(&b);
    __nv_bfloat162 x0 = __hmul2(pa[0], pb[0]);
    __nv_bfloat162 x1 = __hmul2(pa[1], pb[1]);
    __nv_bfloat162 x2 = __hmul2(pa[2], pb[2]);
    __nv_bfloat162 x3 = __hmul2(pa[3], pb[3]);
    uint4 r;
    r.x = *reinterpret_cast<uint32_t*>(&x0);
    r.y = *reinterpret_cast<uint32_t*>(&x1);
    r.z = *reinterpret_cast<uint32_t*>(&x2);
    r.w = *reinterpret_cast<uint32_t*>(&x3);
    return r;
}

// ---------------------------------------------------------------------------
// proj + convert: warp per 2 rows (MLP 4). Single vectorized read feeds both
// projection and bf16 conversion.  Pt layout: [c][h][j][lane].
// ---------------------------------------------------------------------------
__global__ __launch_bounds__(512)
void proj_conv(const float* __restrict__ route_table,
               const float* __restrict__ time_table,
               const float* __restrict__ mode_a,
               const float* __restrict__ mode_b,
               float* __restrict__ ra_tab, float* __restrict__ tb_tab,
               __nv_bfloat16* __restrict__ rtb, __nv_bfloat16* __restrict__ ttb,
               int n_routes, int n_time)
{
    __shared__ float PtA[CDIM * 2 * 4 * 32];
    __shared__ float PtB[CDIM * 2 * 4 * 32];
    const int tid = threadIdx.x;
    for (int i = tid; i < CDIM * 2 * 4 * 32; i += 512) {
        const int ln = i & 31, j = (i >> 5) & 3, h = (i >> 7) & 1, c = i >> 8;
        const int d = h * 128 + 4 * ln + j;
        PtA[i] = __ldg(mode_a + d * CDIM + c);
        PtB[i] = __ldg(mode_b + d * CDIM + c);
    }
    __syncthreads();

    const int lane  = tid & 31;
    const int total = n_routes + n_time;
    const int row0  = (blockIdx.x * 16 + (tid >> 5)) * 2;
    if (row0 >= total) return;
    const bool has1 = (row0 + 1 < total);
    const int  rowB = has1 ? row0 + 1 : row0;

    const bool isr0 = row0 < n_routes;
    const bool isr1 = rowB < n_routes;
    const float* rf0 = (isr0 ? route_table : time_table)
                       + (size_t)(isr0 ? row0 : row0 - n_routes) * DIM;
    const float* rf1 = (isr1 ? route_table : time_table)
                       + (size_t)(isr1 ? rowB : rowB - n_routes) * DIM;

    const float4* p0 = reinterpret_cast<const float4*>(rf0);
    const float4* p1 = reinterpret_cast<const float4*>(rf1);
    const float4 a0 = __ldg(p0 + lane);
    const float4 a1 = __ldg(p0 + 32 + lane);
    const float4 b0 = __ldg(p1 + lane);
    const float4 b1 = __ldg(p1 + 32 + lane);

#pragma unroll
    for (int rsel = 0; rsel < 2; rsel++) {
        if (rsel == 1 && !has1) break;
        const int  row  = rsel ? rowB : row0;
        const bool is_r = rsel ? isr1 : isr0;
        const int  lrow = is_r ? row : row - n_routes;
        const float4 v0 = rsel ? b0 : a0;
        const float4 v1 = rsel ? b1 : a1;
        const float* Pt = is_r ? PtA : PtB;

        uint2* brow = reinterpret_cast<uint2*>((is_r ? rtb : ttb) + (size_t)lrow * DIM);
        brow[lane]      = make_uint2(pack_bf16(v0.x, v0.y), pack_bf16(v0.z, v0.w));
        brow[lane + 32] = make_uint2(pack_bf16(v1.x, v1.y), pack_bf16(v1.z, v1.w));

        const float vv[2][4] = {{v0.x, v0.y, v0.z, v0.w}, {v1.x, v1.y, v1.z, v1.w}};
        float acc[CDIM] = {0.f, 0.f, 0.f, 0.f, 0.f};
#pragma unroll
        for (int c = 0; c < CDIM; c++)
#pragma unroll
            for (int h = 0; h < 2; h++)
#pragma unroll
                for (int j = 0; j < 4; j++)
                    acc[c] = fmaf(vv[h][j], Pt[((c * 2 + h) * 4 + j) * 32 + lane], acc[c]);

#pragma unroll
        for (int off = 16; off; off >>= 1)
#pragma unroll
            for (int c = 0; c < CDIM; c++) acc[c] += __shfl_xor_sync(0xffffffffu, acc[c], off);

        if (lane == 0) {
            float* o = (is_r ? ra_tab : tb_tab) + (size_t)lrow * CDIM;
#pragma unroll
            for (int c = 0; c < CDIM; c++) o[c] = acc[c];
        }
    }
}

// ---------------------------------------------------------------------------
// Main persistent kernel: 512 threads = 2 independent 256-thread groups.
// Each group: 64-row tiles, double-buffered x, issue/MMA/commit interleave.
// ---------------------------------------------------------------------------
__global__ __launch_bounds__(512, 1)
void main_kernel(const int*   __restrict__ route_idx,
                 const int*   __restrict__ time_idx,
                 const uint4* __restrict__ RTB,
                 const uint4* __restrict__ TTB,
                 const float* __restrict__ w,
                 const float* __restrict__ fc_w,
                 const float* __restrict__ fc_b,
                 const float* __restrict__ mode_bias,
                 const float* __restrict__ ra_tab,
                 const float* __restrict__ tb_tab,
                 float*       __restrict__ out,
                 int batch, int ntiles)
{
    extern __shared__ uint32_t smu[];
    uint32_t* wp  = smu + WP_W;
    float*    fcs = reinterpret_cast<float*>(smu + FCS_W);
    float*    fci = reinterpret_cast<float*>(smu + FCI_W);
    float*    bia = reinterpret_cast<float*>(smu + BIA_W);

    const int tid  = threadIdx.x;
    const int gid  = tid >> 8;            // group 0/1
    const int lt   = tid & 255;
    const int lw   = lt >> 5;             // warp in group (0-7)
    const int lane = tid & 31;
    const uint32_t sm_u32 = smem_u32(smu);

    // stage w bf16-pairs (all 512 threads)
    for (int i = tid; i < 128 * 128; i += 512) {
        const int n = i & 127, kp = i >> 7;
        const float f0 = (n < KOUT) ? __ldg(w + (2 * kp)     * KOUT + n) : 0.f;
        const float f1 = (n < KOUT) ? __ldg(w + (2 * kp + 1) * KOUT + n) : 0.f;
        wp[n * XSTR + kp] = pack_bf16(f0, f1);
    }
    if (tid < 128)                 fcs[tid] = (tid < KOUT) ? __ldg(fc_w + tid) : 0.f;
    if (tid >= 128 && tid < 153)   fci[tid - 128] = __ldg(fc_w + KOUT + tid - 128);
    if (tid >= 160 && tid < 185)   bia[tid - 160] = __ldg(mode_bias + tid - 160);
    if (tid < 128)                 reinterpret_cast<float*>(smu + OAC_W)[tid] = 0.f;

    const float fcb = __ldg(fc_b);

    float* oacg = reinterpret_cast<float*>(smu + OAC_W) + gid * 64;
    uint32_t* xg = smu + XB_W + gid * (2 * 64 * XSTR);
    float* rv5g  = reinterpret_cast<float*>(smu + RV5_W) + gid * (2 * 64 * CDIM);
    float* tv5g  = reinterpret_cast<float*>(smu + TV5_W) + gid * (2 * 64 * CDIM);

    const int mq = lw >> 2, nq = lw & 3;       // warp tile: rows mq*32+{0,16}, cols nq*32
    const int t  = lane & 3;
    const int barid = 1 + gid;

    // ldmatrix addressing
    const int a_row   = (lane & 7) + ((lane >> 3) & 1) * 8;
    const int a_khalf = (lane >> 4) * 4;
    const int b_n     = ((lane >> 4) << 3) + (lane & 7);
    const int b_khalf = ((lane >> 3) & 1) * 4;
    uint32_t bAddr[2];
#pragma unroll
    for (int p = 0; p < 2; p++)
        bAddr[p] = sm_u32 + (WP_W + (nq * 32 + p * 16 + b_n) * XSTR + b_khalf) * 4;

    const int step  = gridDim.x * 2;
    const int first = blockIdx.x * 2 + gid;
    const int li    = lane & 7;

    __syncthreads();   // w staged

    // ---- prologue: full gather of first tile into slot 0 ----
    {
        const int ei = min(first * 64 + lw * 8 + li, batch - 1);
        const int ridx = __ldg(route_idx + ei);
        const int tidx = __ldg(time_idx  + ei);
        if (lane < 8) {
#pragma unroll
            for (int c = 0; c < CDIM; c++) {
                rv5g[(lw * 8 + li) * CDIM + c] = __ldg(ra_tab + (size_t)ridx * CDIM + c);
                tv5g[(lw * 8 + li) * CDIM + c] = __ldg(tb_tab + (size_t)tidx * CDIM + c);
            }
        }
#pragma unroll
        for (int h = 0; h < 2; h++) {
            uint4 rr[4], tt[4];
#pragma unroll
            for (int i = 0; i < 4; i++) {
                const int r0 = __shfl_sync(0xffffffffu, ridx, h * 4 + i);
                const int t0 = __shfl_sync(0xffffffffu, tidx, h * 4 + i);
                rr[i] = __ldg(RTB + (size_t)r0 * 32 + lane);
                tt[i] = __ldg(TTB + (size_t)t0 * 32 + lane);
            }
#pragma unroll
            for (int i = 0; i < 4; i++)
                *reinterpret_cast<uint4*>(xg + (lw * 8 + h * 4 + i) * XSTR + 4 * lane)
                    = hmul8(rr[i], tt[i]);
        }
    }
    BARG(barid);

    int it = 0;
    for (int tile = first; tile < ntiles; tile += step, it++) {
        const int s = it & 1;
        uint32_t* xb_cur = xg + s * (64 * XSTR);
        uint32_t* xb_nxt = xg + (s ^ 1) * (64 * XSTR);
        const bool have_next = (tile + step < ntiles);
        const int  ntile = tile + step;

        int nridx = 0, ntidx = 0;
        uint4 rr[4], tt[4];

        // ---- issue next-tile idx + rows 0-3 ----
        if (have_next) {
            const int ei = min(ntile * 64 + lw * 8 + li, batch - 1);
            nridx = __ldg(route_idx + ei);
            ntidx = __ldg(time_idx  + ei);
#pragma unroll
            for (int i = 0; i < 4; i++) {
                const int r0 = __shfl_sync(0xffffffffu, nridx, i);
                const int t0 = __shfl_sync(0xffffffffu, ntidx, i);
                rr[i] = __ldg(RTB + (size_t)r0 * 32 + lane);
                tt[i] = __ldg(TTB + (size_t)t0 * 32 + lane);
            }
            if (lane < 8) {
#pragma unroll
                for (int c = 0; c < CDIM; c++) {
                    rv5g[((s ^ 1) * 64 + lw * 8 + li) * CDIM + c]
                        = __ldg(ra_tab + (size_t)nridx * CDIM + c);
                    tv5g[((s ^ 1) * 64 + lw * 8 + li) * CDIM + c]
                        = __ldg(tb_tab + (size_t)ntidx * CDIM + c);
                }
            }
        }

        // ---- MMA setup ----
        float acc[2][4][4];
#pragma unroll
        for (int m = 0; m < 2; m++)
#pragma unroll
            for (int n = 0; n < 4; n++)
#pragma unroll
                for (int q = 0; q < 4; q++) acc[m][n][q] = 0.f;

        uint32_t aAddr[2];
#pragma unroll
        for (int m = 0; m < 2; m++)
            aAddr[m] = sm_u32 + (uint32_t)((xb_cur - smu)
                       + (mq * 32 + m * 16 + a_row) * XSTR + a_khalf) * 4;

        // ---- MMA kc 0-7 (hides next-tile LDG latency) ----
#pragma unroll 2
        for (int kc = 0; kc < 8; kc++) {
            const uint32_t kb = kc * 32;
            uint32_t bb[8];
            LDSM_X4(bb[0], bb[1], bb[2], bb[3], bAddr[0] + kb);
            LDSM_X4(bb[4], bb[5], bb[6], bb[7], bAddr[1] + kb);
#pragma unroll
            for (int m = 0; m < 2; m++) {
                uint32_t a[4];
                LDSM_X4(a[0], a[1], a[2], a[3], aAddr[m] + kb);
                mma_bf16(acc[m][0], a, bb[0], bb[1]);
                mma_bf16(acc[m][1], a, bb[2], bb[3]);
                mma_bf16(acc[m][2], a, bb[4], bb[5]);
                mma_bf16(acc[m][3], a, bb[6], bb[7]);
            }
        }

        // ---- commit rows 0-3; issue rows 4-7 ----
        if (have_next) {
#pragma unroll
            for (int i = 0; i < 4; i++)
                *reinterpret_cast<uint4*>(xb_nxt + (lw * 8 + i) * XSTR + 4 * lane)
                    = hmul8(rr[i], tt[i]);
#pragma unroll
            for (int i = 0; i < 4; i++) {
                const int r0 = __shfl_sync(0xffffffffu, nridx, 4 + i);
                const int t0 = __shfl_sync(0xffffffffu, ntidx, 4 + i);
                rr[i] = __ldg(RTB + (size_t)r0 * 32 + lane);
                tt[i] = __ldg(TTB + (size_t)t0 * 32 + lane);
            }
        }

        // ---- MMA kc 8-15 ----
#pragma unroll 2
        for (int kc = 8; kc < 16; kc++) {
            const uint32_t kb = kc * 32;
            uint32_t bb[8];
            LDSM_X4(bb[0], bb[1], bb[2], bb[3], bAddr[0] + kb);
            LDSM_X4(bb[4], bb[5], bb[6], bb[7], bAddr[1] + kb);
#pragma unroll
            for (int m = 0; m < 2; m++) {
                uint32_t a[4];
                LDSM_X4(a[0], a[1], a[2], a[3], aAddr[m] + kb);
                mma_bf16(acc[m][0], a, bb[0], bb[1]);
                mma_bf16(acc[m][1], a, bb[2], bb[3]);
                mma_bf16(acc[m][2], a, bb[4], bb[5]);
                mma_bf16(acc[m][3], a, bb[6], bb[7]);
            }
        }

        // ---- commit rows 4-7 ----
        if (have_next) {
#pragma unroll
            for (int i = 0; i < 4; i++)
                *reinterpret_cast<uint4*>(xb_nxt + (lw * 8 + 4 + i) * XSTR + 4 * lane)
                    = hmul8(rr[i], tt[i]);
        }

        // ---- fold relu * fc_w -> per-row partials ----
#pragma unroll
        for (int m = 0; m < 2; m++) {
            float p0 = 0.f, p1 = 0.f;
#pragma unroll
            for (int n = 0; n < 4; n++) {
                const int col = nq * 32 + n * 8 + 2 * t;
                const float f0 = fcs[col], f1 = fcs[col + 1];
                p0 = fmaf(f0, fmaxf(acc[m][n][0], 0.f), p0);
                p0 = fmaf(f1, fmaxf(acc[m][n][1], 0.f), p0);
                p1 = fmaf(f0, fmaxf(acc[m][n][2], 0.f), p1);
                p1 = fmaf(f1, fmaxf(acc[m][n][3], 0.f), p1);
            }
            p0 += __shfl_xor_sync(0xffffffffu, p0, 1);
            p0 += __shfl_xor_sync(0xffffffffu, p0, 2);
            p1 += __shfl_xor_sync(0xffffffffu, p1, 1);
            p1 += __shfl_xor_sync(0xffffffffu, p1, 2);
            if (t == 0) {
                const int row = mq * 32 + m * 16 + (lane >> 2);
                atomicAdd(oacg + row, p0);
                atomicAdd(oacg + row + 8, p1);
            }
        }
        BARG(barid);   // partials complete

        // ---- epilogue: 4 threads per row, 7/6/6/6 sigmoid terms ----
        {
            const int row = lt >> 2;
            const int p   = lt & 3;
            const int eo  = tile * 64 + row;
            const float* rv = rv5g + (s * 64 + row) * CDIM;
            const float* tv = tv5g + (s * 64 + row) * CDIM;
            const int start = p ? (1 + p * 6) : 0;
            const int cnt   = p ? 6 : 7;
            float val = 0.f;
#pragma unroll
            for (int k = 0; k < 7; k++) {
                if (k < cnt) {
                    const int idx = start + k;
                    const int i5  = idx / 5, j5 = idx - 5 * i5;
                    const float x  = fmaf(rv[i5], tv[j5], bia[idx]);
                    const float sg = 1.0f / (1.0f + __expf(-x));
                    val = fmaf(fci[idx], sg, val);
                }
            }
            val += __shfl_xor_sync(0xffffffffu, val, 1);
            val += __shfl_xor_sync(0xffffffffu, val, 2);
            if (p == 0) {
                if (eo < batch) out[eo] = fcb + oacg[row] + val;
                oacg[row] = 0.f;
            }
        }
        BARG(barid);   // oac reset visible; next tile may proceed
    }
}

// ---------------------------------------------------------------------------
extern "C" void kernel_launch(void* const* d_in, const int* in_sizes, int n_in,
                              void* d_out, int out_size)
{
    const int*   route_idx   = (const int*)  d_in[0];
    const int*   time_idx    = (const int*)  d_in[1];
    const float* route_table = (const float*)d_in[2];
    const float* time_table  = (const float*)d_in[3];
    const float* w           = (const float*)d_in[4];
    const float* mode_a      = (const float*)d_in[5];
    const float* mode_b      = (const float*)d_in[6];
    const float* mode_bias   = (const float*)d_in[7];
    const float* fc_w        = (const float*)d_in[8];
    const float* fc_b        = (const float*)d_in[9];
    float*       out         = (float*)d_out;

    const int batch    = in_sizes[0];
    const int n_routes = in_sizes[2] / DIM;
    const int n_time   = in_sizes[3] / DIM;

    float *ra_ptr = nullptr, *tb_ptr = nullptr;
    __nv_bfloat16 *rtb_ptr = nullptr, *ttb_ptr = nullptr;
    cudaGetSymbolAddress((void**)&ra_ptr,  g_ra);
    cudaGetSymbolAddress((void**)&tb_ptr,  g_tb);
    cudaGetSymbolAddress((void**)&rtb_ptr, g_rtb);
    cudaGetSymbolAddress((void**)&ttb_ptr, g_ttb);

    {
        const int total = n_routes + n_time;
        proj_conv<<<(total + 31) / 32, 512>>>(route_table, time_table, mode_a, mode_b,
                                              ra_ptr, tb_ptr, rtb_ptr, ttb_ptr,
                                              n_routes, n_time);
    }

    const int ntiles = (batch + 63) / 64;
    const int smem_bytes = SM_WORDS * 4;   // 214272
    cudaFuncSetAttribute(main_kernel, cudaFuncAttributeMaxDynamicSharedMemorySize, smem_bytes);

    int grid = 148;
    main_kernel<<<grid, 512, smem_bytes>>>(route_idx, time_idx,
                                           (const uint4*)rtb_ptr, (const uint4*)ttb_ptr,
                                           w, fc_w, fc_b, mode_bias,
                                           ra_ptr, tb_ptr, out, batch, ntiles);
}